// round 1
// baseline (speedup 1.0000x reference)
#include <cuda_runtime.h>
#include <cuda_bf16.h>
#include <math.h>

// Problem constants
#define S 2048
#define D 1024
#define H 16
#define HD 64
#define DF 4096
#define NL 2
#define VOCAB 32000
#define HALFW 128           // W//2
#define ATT_SCALE 0.125f    // 1/sqrt(64)
#define LN_EPS 1e-5f

// ---------------- scratch (device globals; allocation-free) ----------------
__device__ float g_x[S * D];      // residual stream
__device__ float g_h[S * D];      // layernorm output
__device__ float g_q[S * D];
__device__ float g_k[S * D];
__device__ float g_v[S * D];
__device__ float g_att[S * D];    // attention output (pre-proj)
__device__ float g_ffn[S * DF];   // ffn intermediate

// ---------------- embedding: x = emb[ids] + pos ----------------
__global__ void embed_kernel(const int* __restrict__ ids,
                             const float* __restrict__ emb,
                             const float* __restrict__ pos) {
    int idx = blockIdx.x * blockDim.x + threadIdx.x;
    if (idx >= S * D) return;
    int s = idx >> 10;          // /D
    int d = idx & (D - 1);
    g_x[idx] = emb[(size_t)ids[s] * D + d] + pos[idx];
}

// ---------------- layernorm: out = (x-mu)*rsqrt(var+eps)*g + b ----------------
__global__ __launch_bounds__(256) void ln_kernel(const float* __restrict__ x,
                                                 float* __restrict__ out,
                                                 const float* __restrict__ g,
                                                 const float* __restrict__ b) {
    __shared__ float rs[256], rs2[256];
    int row = blockIdx.x;
    int t = threadIdx.x;
    const float* xr = x + (size_t)row * D;
    float s = 0.f, s2 = 0.f;
#pragma unroll
    for (int i = t; i < D; i += 256) {
        float v = xr[i];
        s += v; s2 += v * v;
    }
    rs[t] = s; rs2[t] = s2;
    __syncthreads();
    for (int off = 128; off > 0; off >>= 1) {
        if (t < off) { rs[t] += rs[t + off]; rs2[t] += rs2[t + off]; }
        __syncthreads();
    }
    float mu = rs[0] * (1.0f / D);
    float var = rs2[0] * (1.0f / D) - mu * mu;
    float inv = rsqrtf(var + LN_EPS);
    float* orow = out + (size_t)row * D;
#pragma unroll
    for (int i = t; i < D; i += 256) {
        orow[i] = (xr[i] - mu) * inv * g[i] + b[i];
    }
}

// ---------------- SGEMM 128x128x8, 8x8 per thread ----------------
// C = A(MxK) * B + bias [+ residual], optional exact GELU, optional B^T (B is NxK)
// All dims divisible: M=2048, N in {1024,4096,32000}, K in {1024,4096}.
#define BM 128
#define BN 128
#define BK 8

__device__ __forceinline__ float gelu_exact(float v) {
    return 0.5f * v * (1.0f + erff(v * 0.70710678118654752f));
}

template<bool TRANSB, bool DO_GELU, bool DO_RES, bool HAS_BIAS>
__global__ __launch_bounds__(256) void sgemm_kernel(
    const float* __restrict__ A, const float* __restrict__ B,
    const float* __restrict__ bias, const float* __restrict__ res,
    float* __restrict__ C, int M, int N, int K)
{
    __shared__ float As[BK][BM];
    __shared__ float Bs[BK][BN];
    const int tid = threadIdx.x;
    const int bm = blockIdx.y * BM;
    const int bn = blockIdx.x * BN;

    // A tile load mapping: 128 rows x 8 k, one float4 per thread
    const int a_row = tid >> 1;
    const int a_col = (tid & 1) * 4;
    // B (NN) tile load: 8 k-rows x 128 n, one float4 per thread
    const int bnn_k = tid >> 5;
    const int bnn_n = (tid & 31) * 4;
    // B (NT) tile load: 128 n-rows x 8 k
    const int bt_n = tid >> 1;
    const int bt_k = (tid & 1) * 4;

    const int tx = tid & 15;
    const int ty = tid >> 4;

    float acc[8][8];
#pragma unroll
    for (int i = 0; i < 8; ++i)
#pragma unroll
        for (int j = 0; j < 8; ++j) acc[i][j] = 0.f;

    for (int k0 = 0; k0 < K; k0 += BK) {
        float4 av = *(const float4*)(A + (size_t)(bm + a_row) * K + k0 + a_col);
        As[a_col + 0][a_row] = av.x;
        As[a_col + 1][a_row] = av.y;
        As[a_col + 2][a_row] = av.z;
        As[a_col + 3][a_row] = av.w;
        if (TRANSB) {
            float4 bv = *(const float4*)(B + (size_t)(bn + bt_n) * K + k0 + bt_k);
            Bs[bt_k + 0][bt_n] = bv.x;
            Bs[bt_k + 1][bt_n] = bv.y;
            Bs[bt_k + 2][bt_n] = bv.z;
            Bs[bt_k + 3][bt_n] = bv.w;
        } else {
            float4 bv = *(const float4*)(B + (size_t)(k0 + bnn_k) * N + bn + bnn_n);
            *(float4*)&Bs[bnn_k][bnn_n] = bv;
        }
        __syncthreads();
#pragma unroll
        for (int k = 0; k < BK; ++k) {
            float rm[8], rn[8];
            float4 m0 = *(const float4*)&As[k][ty * 4];
            float4 m1 = *(const float4*)&As[k][64 + ty * 4];
            rm[0] = m0.x; rm[1] = m0.y; rm[2] = m0.z; rm[3] = m0.w;
            rm[4] = m1.x; rm[5] = m1.y; rm[6] = m1.z; rm[7] = m1.w;
            float4 n0 = *(const float4*)&Bs[k][tx * 4];
            float4 n1 = *(const float4*)&Bs[k][64 + tx * 4];
            rn[0] = n0.x; rn[1] = n0.y; rn[2] = n0.z; rn[3] = n0.w;
            rn[4] = n1.x; rn[5] = n1.y; rn[6] = n1.z; rn[7] = n1.w;
#pragma unroll
            for (int i = 0; i < 8; ++i)
#pragma unroll
                for (int j = 0; j < 8; ++j)
                    acc[i][j] += rm[i] * rn[j];
        }
        __syncthreads();
    }

    // epilogue: rows {ty*4+i, 64+ty*4+i}, cols {tx*4+j, 64+tx*4+j}
#pragma unroll
    for (int ih = 0; ih < 2; ++ih) {
#pragma unroll
        for (int i = 0; i < 4; ++i) {
            int row = bm + ih * 64 + ty * 4 + i;
#pragma unroll
            for (int jh = 0; jh < 2; ++jh) {
                int col0 = bn + jh * 64 + tx * 4;
                float4 v;
                float vv[4];
#pragma unroll
                for (int j = 0; j < 4; ++j) {
                    float val = acc[ih * 4 + i][jh * 4 + j];
                    if (HAS_BIAS) val += bias[col0 + j];
                    if (DO_GELU) val = gelu_exact(val);
                    vv[j] = val;
                }
                if (DO_RES) {
                    float4 r = *(const float4*)(res + (size_t)row * N + col0);
                    vv[0] += r.x; vv[1] += r.y; vv[2] += r.z; vv[3] += r.w;
                }
                v.x = vv[0]; v.y = vv[1]; v.z = vv[2]; v.w = vv[3];
                *(float4*)(C + (size_t)row * N + col0) = v;
            }
        }
    }
}

// ---------------- local banded attention ----------------
// grid (S, H), 64 threads. scores j-parallel, output d-parallel (coalesced V).
__global__ __launch_bounds__(64) void attn_kernel(const float* __restrict__ q,
                                                  const float* __restrict__ k,
                                                  const float* __restrict__ v,
                                                  float* __restrict__ out) {
    __shared__ float qv[HD];
    __shared__ float sc[2 * HALFW + 1];
    __shared__ float red[64];
    const int qi = blockIdx.x;
    const int head = blockIdx.y;
    const int t = threadIdx.x;
    const int base = head * HD;

    qv[t] = q[(size_t)qi * D + base + t];
    __syncthreads();

    const int jlo = max(qi - HALFW, 0);
    const int jhi = min(qi + HALFW, S - 1);
    const int nj = jhi - jlo + 1;

    for (int jj = t; jj < nj; jj += 64) {
        const float* kr = k + (size_t)(jlo + jj) * D + base;
        float dot = 0.f;
#pragma unroll
        for (int d = 0; d < HD; ++d) dot += qv[d] * kr[d];
        sc[jj] = dot * ATT_SCALE;
    }
    __syncthreads();

    // max reduce
    float lm = -1e30f;
    for (int jj = t; jj < nj; jj += 64) lm = fmaxf(lm, sc[jj]);
    red[t] = lm;
    __syncthreads();
    for (int off = 32; off > 0; off >>= 1) {
        if (t < off) red[t] = fmaxf(red[t], red[t + off]);
        __syncthreads();
    }
    float mx = red[0];
    __syncthreads();

    // exp + sum reduce
    float ls = 0.f;
    for (int jj = t; jj < nj; jj += 64) {
        float e = __expf(sc[jj] - mx);
        sc[jj] = e;
        ls += e;
    }
    red[t] = ls;
    __syncthreads();
    for (int off = 32; off > 0; off >>= 1) {
        if (t < off) red[t] += red[t + off];
        __syncthreads();
    }
    float denom = red[0];
    __syncthreads();

    // output: thread t owns dim t
    float accv = 0.f;
    for (int jj = 0; jj < nj; ++jj) {
        accv += sc[jj] * v[(size_t)(jlo + jj) * D + base + t];
    }
    out[(size_t)qi * D + base + t] = accv / denom;
}

// ---------------- host orchestration ----------------
static void launch_gemm_nn(const float* A, const float* B, const float* bias,
                           float* C, int M, int N, int K) {
    dim3 grid(N / BN, M / BM);
    sgemm_kernel<false, false, false, true><<<grid, 256>>>(A, B, bias, nullptr, C, M, N, K);
}
static void launch_gemm_nn_res(const float* A, const float* B, const float* bias,
                               const float* res, float* C, int M, int N, int K) {
    dim3 grid(N / BN, M / BM);
    sgemm_kernel<false, false, true, true><<<grid, 256>>>(A, B, bias, res, C, M, N, K);
}
static void launch_gemm_nn_gelu(const float* A, const float* B, const float* bias,
                                float* C, int M, int N, int K) {
    dim3 grid(N / BN, M / BM);
    sgemm_kernel<false, true, false, true><<<grid, 256>>>(A, B, bias, nullptr, C, M, N, K);
}
static void launch_gemm_nt(const float* A, const float* B, float* C,
                           int M, int N, int K) {
    dim3 grid(N / BN, M / BM);
    sgemm_kernel<true, false, false, false><<<grid, 256>>>(A, B, nullptr, nullptr, C, M, N, K);
}

extern "C" void kernel_launch(void* const* d_in, const int* in_sizes, int n_in,
                              void* d_out, int out_size) {
    const int*   ids   = (const int*)  d_in[0];
    const float* emb   = (const float*)d_in[1];
    const float* pos   = (const float*)d_in[2];
    const float* wq    = (const float*)d_in[3];
    const float* bq    = (const float*)d_in[4];
    const float* wk    = (const float*)d_in[5];
    const float* bk    = (const float*)d_in[6];
    const float* wv    = (const float*)d_in[7];
    const float* bv    = (const float*)d_in[8];
    const float* wo    = (const float*)d_in[9];
    const float* bo    = (const float*)d_in[10];
    const float* w1    = (const float*)d_in[11];
    const float* b1    = (const float*)d_in[12];
    const float* w2    = (const float*)d_in[13];
    const float* b2    = (const float*)d_in[14];
    const float* ln1_g = (const float*)d_in[15];
    const float* ln1_b = (const float*)d_in[16];
    const float* ln2_g = (const float*)d_in[17];
    const float* ln2_b = (const float*)d_in[18];
    const float* out_g = (const float*)d_in[19];
    const float* out_b = (const float*)d_in[20];
    float* logits = (float*)d_out;

    float *x, *h, *q, *k, *v, *att, *ffn;
    cudaGetSymbolAddress((void**)&x,   g_x);
    cudaGetSymbolAddress((void**)&h,   g_h);
    cudaGetSymbolAddress((void**)&q,   g_q);
    cudaGetSymbolAddress((void**)&k,   g_k);
    cudaGetSymbolAddress((void**)&v,   g_v);
    cudaGetSymbolAddress((void**)&att, g_att);
    cudaGetSymbolAddress((void**)&ffn, g_ffn);

    // embedding
    embed_kernel<<<(S * D + 255) / 256, 256>>>(ids, emb, pos);

    for (int l = 0; l < NL; ++l) {
        const float* wq_l = wq + (size_t)l * D * D;
        const float* wk_l = wk + (size_t)l * D * D;
        const float* wv_l = wv + (size_t)l * D * D;
        const float* wo_l = wo + (size_t)l * D * D;
        const float* w1_l = w1 + (size_t)l * D * DF;
        const float* w2_l = w2 + (size_t)l * DF * D;

        // h = LN1(x)
        ln_kernel<<<S, 256>>>(x, h, ln1_g + l * D, ln1_b + l * D);
        // q,k,v projections
        launch_gemm_nn(h, wq_l, bq + l * D, q, S, D, D);
        launch_gemm_nn(h, wk_l, bk + l * D, k, S, D, D);
        launch_gemm_nn(h, wv_l, bv + l * D, v, S, D, D);
        // local attention
        {
            dim3 ag(S, H);
            attn_kernel<<<ag, 64>>>(q, k, v, att);
        }
        // x = x + att @ wo + bo
        launch_gemm_nn_res(att, wo_l, bo + l * D, x, x, S, D, D);
        // h = LN2(x)
        ln_kernel<<<S, 256>>>(x, h, ln2_g + l * D, ln2_b + l * D);
        // ffn = gelu(h @ w1 + b1)
        launch_gemm_nn_gelu(h, w1_l, b1 + l * DF, ffn, S, DF, D);
        // x = x + ffn @ w2 + b2
        launch_gemm_nn_res(ffn, w2_l, b2 + l * D, x, x, S, D, DF);
    }

    // final LN
    ln_kernel<<<S, 256>>>(x, h, out_g, out_b);
    // logits = h @ emb^T
    launch_gemm_nt(h, emb, logits, S, VOCAB, D);
}

// round 3
// speedup vs baseline: 4.1109x; 4.1109x over previous
#include <cuda_runtime.h>
#include <math.h>
#include <stdint.h>

// ---------------- problem constants ----------------
#define S 2048
#define D 1024
#define H 16
#define HD 64
#define DF 4096
#define NL 2
#define VOCAB 32000
#define HALFW 128
#define ATT_SCALE 0.125f
#define LN_EPS 1e-5f
#define MB_ELT (1024*1024)

// ---------------- scratch (device globals) ----------------
__device__ float g_x[S * D];
__device__ float g_h[S * D];
__device__ float g_qkv[S * 3 * D];
__device__ float g_att[S * D];
__device__ float g_ffn[S * DF];
__device__ float g_wT[NL * 12 * MB_ELT];   // per layer: qkvT(3M) woT(1M) w1T(4M) w2T(4M)
__device__ float g_embT[VOCAB * D];        // tf32-rounded emb ([N,K] already)
__device__ float g_bqkv[NL * 3 * D];

// ---------------- helpers ----------------
__device__ __forceinline__ uint32_t smem_u32(const void* p) {
    uint32_t a;
    asm("{ .reg .u64 t; cvta.to.shared.u64 t, %1; cvt.u32.u64 %0, t; }" : "=r"(a) : "l"(p));
    return a;
}
__device__ __forceinline__ float to_tf32(float x) {
    uint32_t r;
    asm("cvt.rna.tf32.f32 %0, %1;" : "=r"(r) : "f"(x));
    return __uint_as_float(r);
}
__device__ __forceinline__ void cp16(uint32_t dst, const void* src) {
    asm volatile("cp.async.cg.shared.global [%0], [%1], 16;" :: "r"(dst), "l"(src));
}
__device__ __forceinline__ void cp_commit() {
    asm volatile("cp.async.commit_group;" ::: "memory");
}
template<int N>
__device__ __forceinline__ void cp_wait() {
    asm volatile("cp.async.wait_group %0;" :: "n"(N) : "memory");
}
__device__ __forceinline__ void mma_tf32_16_8_8(float* c, const uint32_t* a, const uint32_t* b) {
    asm volatile(
        "mma.sync.aligned.m16n8k8.row.col.f32.tf32.tf32.f32 "
        "{%0,%1,%2,%3}, {%4,%5,%6,%7}, {%8,%9}, {%0,%1,%2,%3};"
        : "+f"(c[0]), "+f"(c[1]), "+f"(c[2]), "+f"(c[3])
        : "r"(a[0]), "r"(a[1]), "r"(a[2]), "r"(a[3]), "r"(b[0]), "r"(b[1]));
}
__device__ __forceinline__ float gelu_exact(float v) {
    return 0.5f * v * (1.0f + erff(v * 0.70710678118654752f));
}

// ---------------- tf32 mma.sync GEMM: C[2048, N] = A[M,K] * B[N,K]^T ----------------
#define BM 128
#define BN 128
#define BKT 32
#define BKP 36          // padded k-stride (words): conflict-free fragment LDS
#define NSTG 4
#define TILE_F (BM * BKP)   // floats per tile per stage

template<bool HAS_BIAS, bool DO_GELU, bool DO_RES, bool DO_ROUND>
__global__ __launch_bounds__(256) void mma_gemm(
    const float* __restrict__ A, const float* __restrict__ B,
    const float* __restrict__ bias, const float* __restrict__ res,
    float* __restrict__ C, int N_total, int K_total)
{
    extern __shared__ __align__(16) float smf[];
    float* As = smf;                       // [NSTG][BM][BKP]
    float* Bs = smf + NSTG * TILE_F;       // [NSTG][BN][BKP]

    const int tid = threadIdx.x;
    const int bm = blockIdx.x * BM;
    const int bn = blockIdx.y * BN;
    const int wid = tid >> 5, lane = tid & 31;
    const int wm = (wid & 3) * 32;         // warp rows
    const int wn = (wid >> 2) * 64;        // warp cols
    const int grp = lane >> 2, tig = lane & 3;

    const int lrow = tid >> 3;             // 0..31
    const int lcol = (tid & 7) * 4;        // 0,4,...,28

    float acc[2][8][4];
#pragma unroll
    for (int i = 0; i < 2; ++i)
#pragma unroll
        for (int j = 0; j < 8; ++j)
#pragma unroll
            for (int q = 0; q < 4; ++q) acc[i][j][q] = 0.f;

    const int nIter = K_total / BKT;

    // prologue: stages 0..NSTG-2
#pragma unroll
    for (int s = 0; s < NSTG - 1; ++s) {
        int k0 = s * BKT;
        float* Ast = As + s * TILE_F;
        float* Bst = Bs + s * TILE_F;
#pragma unroll
        for (int r = 0; r < 4; ++r) {
            int row = lrow + r * 32;
            cp16(smem_u32(Ast + row * BKP + lcol), A + (size_t)(bm + row) * K_total + k0 + lcol);
            cp16(smem_u32(Bst + row * BKP + lcol), B + (size_t)(bn + row) * K_total + k0 + lcol);
        }
        cp_commit();
    }

    for (int c = 0; c < nIter; ++c) {
        cp_wait<NSTG - 2>();
        __syncthreads();

        // issue load for kIter c+NSTG-1 into stage (c+NSTG-1)%NSTG (computed at iter c-1)
        int nk = c + NSTG - 1;
        if (nk < nIter) {
            int st = nk % NSTG;
            int k0 = nk * BKT;
            float* Ast = As + st * TILE_F;
            float* Bst = Bs + st * TILE_F;
#pragma unroll
            for (int r = 0; r < 4; ++r) {
                int row = lrow + r * 32;
                cp16(smem_u32(Ast + row * BKP + lcol), A + (size_t)(bm + row) * K_total + k0 + lcol);
                cp16(smem_u32(Bst + row * BKP + lcol), B + (size_t)(bn + row) * K_total + k0 + lcol);
            }
        }
        cp_commit();

        // compute stage c%NSTG
        const float* Ast = As + (c % NSTG) * TILE_F + wm * BKP;
        const float* Bst = Bs + (c % NSTG) * TILE_F + wn * BKP;
#pragma unroll
        for (int ks = 0; ks < 4; ++ks) {
            const int k = ks * 8;
            uint32_t af[2][4];
#pragma unroll
            for (int mt = 0; mt < 2; ++mt) {
                const float* ab = Ast + (mt * 16 + grp) * BKP + k + tig;
                af[mt][0] = __float_as_uint(ab[0]);
                af[mt][1] = __float_as_uint(ab[8 * BKP]);
                af[mt][2] = __float_as_uint(ab[4]);
                af[mt][3] = __float_as_uint(ab[8 * BKP + 4]);
            }
            uint32_t bf[8][2];
#pragma unroll
            for (int nt = 0; nt < 8; ++nt) {
                const float* bb = Bst + (nt * 8 + grp) * BKP + k + tig;
                bf[nt][0] = __float_as_uint(bb[0]);
                bf[nt][1] = __float_as_uint(bb[4]);
            }
#pragma unroll
            for (int mt = 0; mt < 2; ++mt)
#pragma unroll
                for (int nt = 0; nt < 8; ++nt)
                    mma_tf32_16_8_8(acc[mt][nt], af[mt], bf[nt]);
        }
    }

    // epilogue
#pragma unroll
    for (int mt = 0; mt < 2; ++mt) {
        const int r0 = bm + wm + mt * 16 + grp;
#pragma unroll
        for (int nt = 0; nt < 8; ++nt) {
            const int cn = bn + wn + nt * 8 + tig * 2;
#pragma unroll
            for (int hh = 0; hh < 2; ++hh) {
                const int row = r0 + hh * 8;
                float v0 = acc[mt][nt][hh * 2 + 0];
                float v1 = acc[mt][nt][hh * 2 + 1];
                if (HAS_BIAS) { v0 += __ldg(&bias[cn]); v1 += __ldg(&bias[cn + 1]); }
                if (DO_GELU) { v0 = gelu_exact(v0); v1 = gelu_exact(v1); }
                if (DO_ROUND) { v0 = to_tf32(v0); v1 = to_tf32(v1); }
                if (DO_RES) {
                    const float2 rv = *(const float2*)(res + (size_t)row * N_total + cn);
                    v0 += rv.x; v1 += rv.y;
                }
                *(float2*)(C + (size_t)row * N_total + cn) = make_float2(v0, v1);
            }
        }
    }
}

// ---------------- small kernels ----------------
__global__ void embed_kernel(const int* __restrict__ ids,
                             const float* __restrict__ emb,
                             const float* __restrict__ pos) {
    int idx = blockIdx.x * blockDim.x + threadIdx.x;
    if (idx >= S * D) return;
    int s = idx >> 10;
    int d = idx & (D - 1);
    g_x[idx] = emb[(size_t)ids[s] * D + d] + pos[idx];
}

__global__ __launch_bounds__(256) void ln_kernel(const float* __restrict__ x,
                                                 float* __restrict__ out,
                                                 const float* __restrict__ g,
                                                 const float* __restrict__ b) {
    __shared__ float rs[256], rs2[256];
    int row = blockIdx.x;
    int t = threadIdx.x;
    const float* xr = x + (size_t)row * D;
    float s = 0.f, s2 = 0.f;
#pragma unroll
    for (int i = t; i < D; i += 256) { float v = xr[i]; s += v; s2 += v * v; }
    rs[t] = s; rs2[t] = s2;
    __syncthreads();
    for (int off = 128; off > 0; off >>= 1) {
        if (t < off) { rs[t] += rs[t + off]; rs2[t] += rs2[t + off]; }
        __syncthreads();
    }
    float mu = rs[0] * (1.0f / D);
    float var = rs2[0] * (1.0f / D) - mu * mu;
    float inv = rsqrtf(var + LN_EPS);
    float* orow = out + (size_t)row * D;
#pragma unroll
    for (int i = t; i < D; i += 256)
        orow[i] = to_tf32((xr[i] - mu) * inv * g[i] + b[i]);  // rounded: feeds tf32 GEMM A
}

__global__ void transpose_round(const float* __restrict__ in, float* __restrict__ out, int R, int C) {
    __shared__ float t[32][33];
    int c0 = blockIdx.x * 32, r0 = blockIdx.y * 32;
    int x = threadIdx.x, y = threadIdx.y;
#pragma unroll
    for (int i = y; i < 32; i += 8) t[i][x] = in[(size_t)(r0 + i) * C + c0 + x];
    __syncthreads();
#pragma unroll
    for (int i = y; i < 32; i += 8) out[(size_t)(c0 + i) * R + r0 + x] = to_tf32(t[x][i]);
}

__global__ void round_copy4(const float4* __restrict__ in, float4* __restrict__ out, int n4) {
    int i = blockIdx.x * blockDim.x + threadIdx.x;
    if (i >= n4) return;
    float4 v = in[i];
    out[i] = make_float4(to_tf32(v.x), to_tf32(v.y), to_tf32(v.z), to_tf32(v.w));
}

__global__ void concat_bias(const float* __restrict__ bq, const float* __restrict__ bk,
                            const float* __restrict__ bv, float* __restrict__ out) {
    int i = blockIdx.x * blockDim.x + threadIdx.x;
    if (i >= 3 * D) return;
    out[i] = (i < D) ? bq[i] : (i < 2 * D) ? bk[i - D] : bv[i - 2 * D];
}

// ---------------- tiled local attention ----------------
// grid (S/64, H), 256 threads. 64 queries x 1 head per block.
// j window per block: [q0-128, q0+191] = 320 positions, 5 tiles of 64.
#define TQ 64
#define JW 320
#define SCP 324

__global__ __launch_bounds__(256) void attn_tiled() {
    extern __shared__ __align__(16) float asm_[];
    float* Qs = asm_;                 // [64][64]
    float* KV = asm_ + 4096;          // [64][64] (K then V tiles)
    float* sc = asm_ + 8192;          // [64][SCP]
    float* invl = sc + 64 * SCP;      // [64]

    const int q0 = blockIdx.x * TQ;
    const int head = blockIdx.y;
    const int tid = threadIdx.x;
    const int RS = 3 * D;
    const int qoff = head * HD, koff = D + head * HD, voff = 2 * D + head * HD;
    const int jbase = q0 - HALFW;

    // load Q tile
    for (int i = tid; i < TQ * 16; i += 256) {
        int row = i >> 4, c4 = (i & 15) * 4;
        *(float4*)&Qs[row * 64 + c4] =
            *(const float4*)&g_qkv[(size_t)(q0 + row) * RS + qoff + c4];
    }

    const int ttq = (tid >> 4) << 2;   // q quad base (0..60)
    const int ttj = (tid & 15) << 2;   // j/d quad base (0..60)

    // ---- scores ----
#pragma unroll 1
    for (int jt = 0; jt < 5; ++jt) {
        __syncthreads();
        for (int i = tid; i < TQ * 16; i += 256) {
            int row = i >> 4, c4 = (i & 15) * 4;
            int j = jbase + jt * 64 + row;
            j = min(max(j, 0), S - 1);
            *(float4*)&KV[row * 64 + c4] =
                *(const float4*)&g_qkv[(size_t)j * RS + koff + c4];
        }
        __syncthreads();
        float a[4][4];
#pragma unroll
        for (int i = 0; i < 4; ++i)
#pragma unroll
            for (int j = 0; j < 4; ++j) a[i][j] = 0.f;
#pragma unroll
        for (int d = 0; d < 64; d += 4) {
            float4 qv[4], kv[4];
#pragma unroll
            for (int i = 0; i < 4; ++i) {
                qv[i] = *(const float4*)&Qs[(ttq + i) * 64 + d];
                kv[i] = *(const float4*)&KV[(ttj + i) * 64 + d];
            }
#pragma unroll
            for (int i = 0; i < 4; ++i)
#pragma unroll
                for (int j = 0; j < 4; ++j)
                    a[i][j] += qv[i].x * kv[j].x + qv[i].y * kv[j].y +
                               qv[i].z * kv[j].z + qv[i].w * kv[j].w;
        }
#pragma unroll
        for (int i = 0; i < 4; ++i)
#pragma unroll
            for (int j = 0; j < 4; ++j) {
                int qq = ttq + i;
                int jj = jt * 64 + ttj + j;
                int jg = jbase + jj;
                int qg = q0 + qq;
                bool ok = (jg >= 0) && (jg < S) && (abs(qg - jg) <= HALFW);
                sc[qq * SCP + jj] = ok ? a[i][j] * ATT_SCALE : -1e30f;
            }
    }
    __syncthreads();

    // ---- softmax (warp w owns rows w*8..w*8+7) ----
    const int wid = tid >> 5, lane = tid & 31;
    for (int r = 0; r < 8; ++r) {
        int q = wid * 8 + r;
        float m = -1e30f;
        for (int j = lane; j < JW; j += 32) m = fmaxf(m, sc[q * SCP + j]);
#pragma unroll
        for (int off = 16; off > 0; off >>= 1) m = fmaxf(m, __shfl_xor_sync(0xffffffffu, m, off));
        float s = 0.f;
        for (int j = lane; j < JW; j += 32) {
            float e = __expf(sc[q * SCP + j] - m);
            sc[q * SCP + j] = e;
            s += e;
        }
#pragma unroll
        for (int off = 16; off > 0; off >>= 1) s += __shfl_xor_sync(0xffffffffu, s, off);
        if (lane == 0) invl[q] = 1.0f / s;
    }
    __syncthreads();

    // ---- AV ----
    float o[4][4];
#pragma unroll
    for (int i = 0; i < 4; ++i)
#pragma unroll
        for (int j = 0; j < 4; ++j) o[i][j] = 0.f;
#pragma unroll 1
    for (int jt = 0; jt < 5; ++jt) {
        __syncthreads();
        for (int i = tid; i < TQ * 16; i += 256) {
            int row = i >> 4, c4 = (i & 15) * 4;
            int j = jbase + jt * 64 + row;
            j = min(max(j, 0), S - 1);
            *(float4*)&KV[row * 64 + c4] =
                *(const float4*)&g_qkv[(size_t)j * RS + voff + c4];
        }
        __syncthreads();
#pragma unroll 4
        for (int jj = 0; jj < 64; ++jj) {
            float4 vv = *(const float4*)&KV[jj * 64 + ttj];
            float p[4];
#pragma unroll
            for (int i = 0; i < 4; ++i) p[i] = sc[(ttq + i) * SCP + jt * 64 + jj];
#pragma unroll
            for (int i = 0; i < 4; ++i) {
                o[i][0] += p[i] * vv.x;
                o[i][1] += p[i] * vv.y;
                o[i][2] += p[i] * vv.z;
                o[i][3] += p[i] * vv.w;
            }
        }
    }
#pragma unroll
    for (int i = 0; i < 4; ++i) {
        int q = ttq + i;
        float il = invl[q];
        float4 r = make_float4(to_tf32(o[i][0] * il), to_tf32(o[i][1] * il),
                               to_tf32(o[i][2] * il), to_tf32(o[i][3] * il));
        *(float4*)&g_att[(size_t)(q0 + q) * D + qoff + ttj] = r;
    }
}

// ---------------- host ----------------
extern "C" void kernel_launch(void* const* d_in, const int* in_sizes, int n_in,
                              void* d_out, int out_size) {
    const int*   ids   = (const int*)  d_in[0];
    const float* emb   = (const float*)d_in[1];
    const float* pos   = (const float*)d_in[2];
    const float* wq    = (const float*)d_in[3];
    const float* bq    = (const float*)d_in[4];
    const float* wk    = (const float*)d_in[5];
    const float* bk    = (const float*)d_in[6];
    const float* wv    = (const float*)d_in[7];
    const float* bv    = (const float*)d_in[8];
    const float* wo    = (const float*)d_in[9];
    const float* bo    = (const float*)d_in[10];
    const float* w1    = (const float*)d_in[11];
    const float* b1    = (const float*)d_in[12];
    const float* w2    = (const float*)d_in[13];
    const float* b2    = (const float*)d_in[14];
    const float* ln1_g = (const float*)d_in[15];
    const float* ln1_b = (const float*)d_in[16];
    const float* ln2_g = (const float*)d_in[17];
    const float* ln2_b = (const float*)d_in[18];
    const float* out_g = (const float*)d_in[19];
    const float* out_b = (const float*)d_in[20];
    float* logits = (float*)d_out;

    float *x, *h, *qkv, *att, *ffn, *wT, *embT, *bqkv;
    cudaGetSymbolAddress((void**)&x,    g_x);
    cudaGetSymbolAddress((void**)&h,    g_h);
    cudaGetSymbolAddress((void**)&qkv,  g_qkv);
    cudaGetSymbolAddress((void**)&att,  g_att);
    cudaGetSymbolAddress((void**)&ffn,  g_ffn);
    cudaGetSymbolAddress((void**)&wT,   g_wT);
    cudaGetSymbolAddress((void**)&embT, g_embT);
    cudaGetSymbolAddress((void**)&bqkv, g_bqkv);

    // smem sizes
    const int GEMM_SM = NSTG * TILE_F * 2 * 4;                 // 147456 B
    const int ATTN_SM = (4096 + 4096 + 64 * SCP + 64) * 4;     // ~116 KB
    cudaFuncSetAttribute(mma_gemm<true,  false, false, false>, cudaFuncAttributeMaxDynamicSharedMemorySize, GEMM_SM);
    cudaFuncSetAttribute(mma_gemm<true,  false, true,  false>, cudaFuncAttributeMaxDynamicSharedMemorySize, GEMM_SM);
    cudaFuncSetAttribute(mma_gemm<true,  true,  false, true >, cudaFuncAttributeMaxDynamicSharedMemorySize, GEMM_SM);
    cudaFuncSetAttribute(mma_gemm<false, false, false, false>, cudaFuncAttributeMaxDynamicSharedMemorySize, GEMM_SM);
    cudaFuncSetAttribute(attn_tiled, cudaFuncAttributeMaxDynamicSharedMemorySize, ATTN_SM);

    // ---- weight prep: transpose + tf32 round ----
    dim3 tb(32, 8);
    for (int l = 0; l < NL; ++l) {
        float* base = wT + (size_t)l * 12 * MB_ELT;
        transpose_round<<<dim3(D / 32,  D / 32),  tb>>>(wq + (size_t)l * D * D,  base + 0 * MB_ELT, D, D);
        transpose_round<<<dim3(D / 32,  D / 32),  tb>>>(wk + (size_t)l * D * D,  base + 1 * MB_ELT, D, D);
        transpose_round<<<dim3(D / 32,  D / 32),  tb>>>(wv + (size_t)l * D * D,  base + 2 * MB_ELT, D, D);
        transpose_round<<<dim3(D / 32,  D / 32),  tb>>>(wo + (size_t)l * D * D,  base + 3 * MB_ELT, D, D);
        transpose_round<<<dim3(DF / 32, D / 32),  tb>>>(w1 + (size_t)l * D * DF, base + 4 * MB_ELT, D, DF);
        transpose_round<<<dim3(D / 32,  DF / 32), tb>>>(w2 + (size_t)l * DF * D, base + 8 * MB_ELT, DF, D);
        concat_bias<<<(3 * D + 255) / 256, 256>>>(bq + l * D, bk + l * D, bv + l * D, bqkv + l * 3 * D);
    }
    {
        int n4 = VOCAB * D / 4;
        round_copy4<<<(n4 + 255) / 256, 256>>>((const float4*)emb, (float4*)embT, n4);
    }

    // ---- forward ----
    embed_kernel<<<(S * D + 255) / 256, 256>>>(ids, emb, pos);

    for (int l = 0; l < NL; ++l) {
        float* base = wT + (size_t)l * 12 * MB_ELT;

        ln_kernel<<<S, 256>>>(x, h, ln1_g + l * D, ln1_b + l * D);

        // qkv = h @ Wqkv^T + b   (N = 3072)
        mma_gemm<true, false, false, false><<<dim3(S / BM, 3 * D / BN), 256, GEMM_SM>>>(
            h, base + 0 * MB_ELT, bqkv + (size_t)l * 3 * D, nullptr, qkv, 3 * D, D);

        attn_tiled<<<dim3(S / TQ, H), 256, ATTN_SM>>>();

        // x = x + att @ wo^T + bo
        mma_gemm<true, false, true, false><<<dim3(S / BM, D / BN), 256, GEMM_SM>>>(
            att, base + 3 * MB_ELT, bo + (size_t)l * D, x, x, D, D);

        ln_kernel<<<S, 256>>>(x, h, ln2_g + l * D, ln2_b + l * D);

        // ffn = round(gelu(h @ w1^T + b1))
        mma_gemm<true, true, false, true><<<dim3(S / BM, DF / BN), 256, GEMM_SM>>>(
            h, base + 4 * MB_ELT, b1 + (size_t)l * DF, nullptr, ffn, DF, D);

        // x = x + ffn @ w2^T + b2
        mma_gemm<true, false, true, false><<<dim3(S / BM, D / BN), 256, GEMM_SM>>>(
            ffn, base + 8 * MB_ELT, b2 + (size_t)l * D, x, x, D, DF);
    }

    ln_kernel<<<S, 256>>>(x, h, out_g, out_b);

    // logits = h @ emb^T
    mma_gemm<false, false, false, false><<<dim3(S / BM, VOCAB / BN), 256, GEMM_SM>>>(
        h, embT, nullptr, nullptr, logits, VOCAB, D);
}

// round 5
// speedup vs baseline: 5.6740x; 1.3802x over previous
#include <cuda_runtime.h>
#include <cuda_fp16.h>
#include <math.h>
#include <stdint.h>

// ---------------- problem constants ----------------
#define S 2048
#define D 1024
#define H 16
#define HD 64
#define DF 4096
#define NL 2
#define VOCAB 32000
#define HALFW 128
#define ATT_SCALE 0.125f
#define LN_EPS 1e-5f
#define MB_ELT (1024*1024)

// ---------------- scratch (device globals) ----------------
__device__ float  g_x[S * D];               // residual stream (fp32)
__device__ __half g_h[S * D];               // LN output (GEMM A)
__device__ __half g_qkv[S * 3 * D];
__device__ __half g_att[S * D];
__device__ __half g_ffn[S * DF];
__device__ __half g_wT[NL * 12 * MB_ELT];   // per layer: qkvT(3M) woT(1M) w1T(4M) w2T(4M)
__device__ __half g_embT[VOCAB * D];
__device__ float  g_bqkv[NL * 3 * D];

// ---------------- helpers ----------------
__device__ __forceinline__ uint32_t smem_u32(const void* p) {
    uint32_t a;
    asm("{ .reg .u64 t; cvta.to.shared.u64 t, %1; cvt.u32.u64 %0, t; }" : "=r"(a) : "l"(p));
    return a;
}
__device__ __forceinline__ void cp16(uint32_t dst, const void* src) {
    asm volatile("cp.async.cg.shared.global [%0], [%1], 16;" :: "r"(dst), "l"(src));
}
__device__ __forceinline__ void cp_commit() {
    asm volatile("cp.async.commit_group;" ::: "memory");
}
template<int N>
__device__ __forceinline__ void cp_wait() {
    asm volatile("cp.async.wait_group %0;" :: "n"(N) : "memory");
}
__device__ __forceinline__ void ldsm_x4(uint32_t* r, uint32_t addr) {
    asm volatile("ldmatrix.sync.aligned.m8n8.x4.shared.b16 {%0,%1,%2,%3}, [%4];"
        : "=r"(r[0]), "=r"(r[1]), "=r"(r[2]), "=r"(r[3]) : "r"(addr));
}
__device__ __forceinline__ void mma_f16(float* c, const uint32_t* a, const uint32_t* b) {
    asm volatile(
        "mma.sync.aligned.m16n8k16.row.col.f32.f16.f16.f32 "
        "{%0,%1,%2,%3}, {%4,%5,%6,%7}, {%8,%9}, {%0,%1,%2,%3};"
        : "+f"(c[0]), "+f"(c[1]), "+f"(c[2]), "+f"(c[3])
        : "r"(a[0]), "r"(a[1]), "r"(a[2]), "r"(a[3]), "r"(b[0]), "r"(b[1]));
}
__device__ __forceinline__ float gelu_exact(float v) {
    return 0.5f * v * (1.0f + erff(v * 0.70710678118654752f));
}
__device__ __forceinline__ uint32_t pack_half2(float a, float b) {
    __half2 h = __floats2half2_rn(a, b);
    return *(uint32_t*)&h;
}

// ---------------- fp16 mma.sync GEMM: C[2048, N] = A[M,K] * B[N,K]^T ----------------
// tiles 128x128x32, 4-stage cp.async, ldmatrix fragments, fp32 accum.
#define BM 128
#define BN 128
#define BKT 32
#define PADW 20                  // words (uint32) per row: 16 data + 4 pad (conflict-free)
#define TILE_W (BM * PADW)       // words per tile per stage
#define NSTG 4

template<bool OUT_HALF, bool HAS_BIAS, bool DO_GELU, bool DO_RES>
__global__ __launch_bounds__(256) void mma_gemm(
    const __half* __restrict__ A, const __half* __restrict__ B,
    const float* __restrict__ bias, const float* __restrict__ res,
    void* __restrict__ Cout, int N_total, int K_total)
{
    extern __shared__ __align__(16) uint32_t smw[];
    uint32_t* As = smw;                       // [NSTG][BM][PADW]
    uint32_t* Bs = smw + NSTG * TILE_W;

    const int tid = threadIdx.x;
    const int bm = blockIdx.x * BM;
    const int bn = blockIdx.y * BN;
    const int wid = tid >> 5, lane = tid & 31;
    const int wm = (wid & 3) * 32;            // warp rows
    const int wn = (wid >> 2) * 64;           // warp cols
    const int grp = lane >> 2, tig = lane & 3;

    // cp.async mapping: thread t loads row t>>1, chunks (t&1)*2, (t&1)*2+1 (16B each)
    const int lrow = tid >> 1;
    const int lch = (tid & 1) * 2;

    // ldmatrix per-lane byte offsets (relative to tile base)
    const uint32_t a_base = ((uint32_t)(wm + (lane & 15)) * PADW + ((lane >> 4) & 1) * 4) * 4;
    const uint32_t b_base = ((uint32_t)(wn + ((lane >> 4) & 1) * 8 + (lane & 7)) * PADW + ((lane >> 3) & 1) * 4) * 4;

    float acc[2][8][4];
#pragma unroll
    for (int i = 0; i < 2; ++i)
#pragma unroll
        for (int j = 0; j < 8; ++j)
#pragma unroll
            for (int q = 0; q < 4; ++q) acc[i][j][q] = 0.f;

    const int nIter = K_total / BKT;

#pragma unroll
    for (int s = 0; s < NSTG - 1; ++s) {
        int k0 = s * BKT;
        uint32_t* Ast = As + s * TILE_W;
        uint32_t* Bst = Bs + s * TILE_W;
#pragma unroll
        for (int cchunk = 0; cchunk < 2; ++cchunk) {
            int ch = lch + cchunk;
            cp16(smem_u32(Ast + lrow * PADW + ch * 4), A + (size_t)(bm + lrow) * K_total + k0 + ch * 8);
            cp16(smem_u32(Bst + lrow * PADW + ch * 4), B + (size_t)(bn + lrow) * K_total + k0 + ch * 8);
        }
        cp_commit();
    }

    for (int c = 0; c < nIter; ++c) {
        cp_wait<NSTG - 2>();
        __syncthreads();

        int nk = c + NSTG - 1;
        if (nk < nIter) {
            int st = nk % NSTG;
            int k0 = nk * BKT;
            uint32_t* Ast = As + st * TILE_W;
            uint32_t* Bst = Bs + st * TILE_W;
#pragma unroll
            for (int cchunk = 0; cchunk < 2; ++cchunk) {
                int ch = lch + cchunk;
                cp16(smem_u32(Ast + lrow * PADW + ch * 4), A + (size_t)(bm + lrow) * K_total + k0 + ch * 8);
                cp16(smem_u32(Bst + lrow * PADW + ch * 4), B + (size_t)(bn + lrow) * K_total + k0 + ch * 8);
            }
        }
        cp_commit();

        const uint32_t sa = smem_u32(As + (c % NSTG) * TILE_W) + a_base;
        const uint32_t sb = smem_u32(Bs + (c % NSTG) * TILE_W) + b_base;
#pragma unroll
        for (int ks = 0; ks < 2; ++ks) {
            uint32_t af[2][4];
#pragma unroll
            for (int mt = 0; mt < 2; ++mt)
                ldsm_x4(af[mt], sa + (uint32_t)(mt * 16 * PADW * 4 + ks * 32));
            uint32_t bf[8][2];
#pragma unroll
            for (int p = 0; p < 4; ++p) {
                uint32_t r[4];
                ldsm_x4(r, sb + (uint32_t)(p * 16 * PADW * 4 + ks * 32));
                bf[2 * p][0] = r[0]; bf[2 * p][1] = r[1];
                bf[2 * p + 1][0] = r[2]; bf[2 * p + 1][1] = r[3];
            }
#pragma unroll
            for (int mt = 0; mt < 2; ++mt)
#pragma unroll
                for (int nt = 0; nt < 8; ++nt)
                    mma_f16(acc[mt][nt], af[mt], bf[nt]);
        }
    }

    // epilogue
#pragma unroll
    for (int mt = 0; mt < 2; ++mt) {
        const int r0 = bm + wm + mt * 16 + grp;
#pragma unroll
        for (int nt = 0; nt < 8; ++nt) {
            const int cn = bn + wn + nt * 8 + tig * 2;
#pragma unroll
            for (int hh = 0; hh < 2; ++hh) {
                const int row = r0 + hh * 8;
                float v0 = acc[mt][nt][hh * 2 + 0];
                float v1 = acc[mt][nt][hh * 2 + 1];
                if (HAS_BIAS) { v0 += __ldg(&bias[cn]); v1 += __ldg(&bias[cn + 1]); }
                if (DO_GELU) { v0 = gelu_exact(v0); v1 = gelu_exact(v1); }
                if (DO_RES) {
                    const float2 rv = *(const float2*)(res + (size_t)row * N_total + cn);
                    v0 += rv.x; v1 += rv.y;
                }
                if (OUT_HALF) {
                    uint32_t hv = pack_half2(v0, v1);
                    *(uint32_t*)((__half*)Cout + (size_t)row * N_total + cn) = hv;
                } else {
                    *(float2*)((float*)Cout + (size_t)row * N_total + cn) = make_float2(v0, v1);
                }
            }
        }
    }
}

// ---------------- small kernels ----------------
__global__ void embed_kernel(const int* __restrict__ ids,
                             const float* __restrict__ emb,
                             const float* __restrict__ pos) {
    int idx = blockIdx.x * blockDim.x + threadIdx.x;
    if (idx >= S * D) return;
    int s = idx >> 10;
    int d = idx & (D - 1);
    g_x[idx] = emb[(size_t)ids[s] * D + d] + pos[idx];
}

__global__ __launch_bounds__(256) void ln_kernel(const float* __restrict__ x,
                                                 __half* __restrict__ out,
                                                 const float* __restrict__ g,
                                                 const float* __restrict__ b) {
    __shared__ float rs[256], rs2[256];
    int row = blockIdx.x;
    int t = threadIdx.x;
    const float* xr = x + (size_t)row * D;
    float s = 0.f, s2 = 0.f;
#pragma unroll
    for (int i = t; i < D; i += 256) { float v = xr[i]; s += v; s2 += v * v; }
    rs[t] = s; rs2[t] = s2;
    __syncthreads();
    for (int off = 128; off > 0; off >>= 1) {
        if (t < off) { rs[t] += rs[t + off]; rs2[t] += rs2[t + off]; }
        __syncthreads();
    }
    float mu = rs[0] * (1.0f / D);
    float var = rs2[0] * (1.0f / D) - mu * mu;
    float inv = rsqrtf(var + LN_EPS);
    __half* orow = out + (size_t)row * D;
#pragma unroll
    for (int i = t; i < D; i += 256)
        orow[i] = __float2half_rn((xr[i] - mu) * inv * g[i] + b[i]);
}

// transpose fp32 -> half: out[C][R] = half(in[R][C]^T)
__global__ void transpose_half(const float* __restrict__ in, __half* __restrict__ out, int R, int C) {
    __shared__ float t[32][33];
    int c0 = blockIdx.x * 32, r0 = blockIdx.y * 32;
    int x = threadIdx.x, y = threadIdx.y;
#pragma unroll
    for (int i = y; i < 32; i += 8) t[i][x] = in[(size_t)(r0 + i) * C + c0 + x];
    __syncthreads();
#pragma unroll
    for (int i = y; i < 32; i += 8) out[(size_t)(c0 + i) * R + r0 + x] = __float2half_rn(t[x][i]);
}

__global__ void f2h_copy4(const float4* __restrict__ in, __half* __restrict__ out, int n4) {
    int i = blockIdx.x * blockDim.x + threadIdx.x;
    if (i >= n4) return;
    float4 v = in[i];
    uint32_t h0 = pack_half2(v.x, v.y);
    uint32_t h1 = pack_half2(v.z, v.w);
    *(uint2*)(out + (size_t)i * 4) = make_uint2(h0, h1);
}

__global__ void concat_bias(const float* __restrict__ bq, const float* __restrict__ bk,
                            const float* __restrict__ bv, float* __restrict__ out) {
    int i = blockIdx.x * blockDim.x + threadIdx.x;
    if (i >= 3 * D) return;
    out[i] = (i < D) ? bq[i] : (i < 2 * D) ? bk[i - D] : bv[i - 2 * D];
}

// ---------------- tiled local attention ----------------
#define TQ 64
#define JW 320
#define SCP 324

__global__ __launch_bounds__(256) void attn_tiled() {
    extern __shared__ __align__(16) float asm_[];
    float* Qs = asm_;                 // [64][64]
    float* KV = asm_ + 4096;          // [64][64]
    float* sc = asm_ + 8192;          // [64][SCP]
    float* invl = sc + 64 * SCP;      // [64]

    const int q0 = blockIdx.x * TQ;
    const int head = blockIdx.y;
    const int tid = threadIdx.x;
    const int RS = 3 * D;
    const int qoff = head * HD, koff = D + head * HD, voff = 2 * D + head * HD;
    const int jbase = q0 - HALFW;

    // load Q tile (half -> float)
    for (int i = tid; i < TQ * 16; i += 256) {
        int row = i >> 4, c4 = (i & 15) * 4;
        uint2 u = *(const uint2*)&g_qkv[(size_t)(q0 + row) * RS + qoff + c4];
        float2 f0 = __half22float2(*(__half2*)&u.x);
        float2 f1 = __half22float2(*(__half2*)&u.y);
        float* dst = &Qs[row * 64 + c4];
        dst[0] = f0.x; dst[1] = f0.y; dst[2] = f1.x; dst[3] = f1.y;
    }

    const int ttq = (tid >> 4) << 2;
    const int ttj = (tid & 15) << 2;

    // ---- scores ----
#pragma unroll 1
    for (int jt = 0; jt < 5; ++jt) {
        __syncthreads();
        for (int i = tid; i < TQ * 16; i += 256) {
            int row = i >> 4, c4 = (i & 15) * 4;
            int j = jbase + jt * 64 + row;
            j = min(max(j, 0), S - 1);
            uint2 u = *(const uint2*)&g_qkv[(size_t)j * RS + koff + c4];
            float2 f0 = __half22float2(*(__half2*)&u.x);
            float2 f1 = __half22float2(*(__half2*)&u.y);
            float* dst = &KV[row * 64 + c4];
            dst[0] = f0.x; dst[1] = f0.y; dst[2] = f1.x; dst[3] = f1.y;
        }
        __syncthreads();
        float a[4][4];
#pragma unroll
        for (int i = 0; i < 4; ++i)
#pragma unroll
            for (int j = 0; j < 4; ++j) a[i][j] = 0.f;
#pragma unroll
        for (int d = 0; d < 64; d += 4) {
            float4 qv[4], kv[4];
#pragma unroll
            for (int i = 0; i < 4; ++i) {
                qv[i] = *(const float4*)&Qs[(ttq + i) * 64 + d];
                kv[i] = *(const float4*)&KV[(ttj + i) * 64 + d];
            }
#pragma unroll
            for (int i = 0; i < 4; ++i)
#pragma unroll
                for (int j = 0; j < 4; ++j)
                    a[i][j] += qv[i].x * kv[j].x + qv[i].y * kv[j].y +
                               qv[i].z * kv[j].z + qv[i].w * kv[j].w;
        }
#pragma unroll
        for (int i = 0; i < 4; ++i)
#pragma unroll
            for (int j = 0; j < 4; ++j) {
                int qq = ttq + i;
                int jj = jt * 64 + ttj + j;
                int jg = jbase + jj;
                int qg = q0 + qq;
                bool ok = (jg >= 0) && (jg < S) && (abs(qg - jg) <= HALFW);
                sc[qq * SCP + jj] = ok ? a[i][j] * ATT_SCALE : -1e30f;
            }
    }
    __syncthreads();

    // ---- softmax ----
    const int wid = tid >> 5, lane = tid & 31;
    for (int r = 0; r < 8; ++r) {
        int q = wid * 8 + r;
        float m = -1e30f;
        for (int j = lane; j < JW; j += 32) m = fmaxf(m, sc[q * SCP + j]);
#pragma unroll
        for (int off = 16; off > 0; off >>= 1) m = fmaxf(m, __shfl_xor_sync(0xffffffffu, m, off));
        float s = 0.f;
        for (int j = lane; j < JW; j += 32) {
            float e = __expf(sc[q * SCP + j] - m);
            sc[q * SCP + j] = e;
            s += e;
        }
#pragma unroll
        for (int off = 16; off > 0; off >>= 1) s += __shfl_xor_sync(0xffffffffu, s, off);
        if (lane == 0) invl[q] = 1.0f / s;
    }
    __syncthreads();

    // ---- AV ----
    float o[4][4];
#pragma unroll
    for (int i = 0; i < 4; ++i)
#pragma unroll
        for (int j = 0; j < 4; ++j) o[i][j] = 0.f;
#pragma unroll 1
    for (int jt = 0; jt < 5; ++jt) {
        __syncthreads();
        for (int i = tid; i < TQ * 16; i += 256) {
            int row = i >> 4, c4 = (i & 15) * 4;
            int j = jbase + jt * 64 + row;
            j = min(max(j, 0), S - 1);
            uint2 u = *(const uint2*)&g_qkv[(size_t)j * RS + voff + c4];
            float2 f0 = __half22float2(*(__half2*)&u.x);
            float2 f1 = __half22float2(*(__half2*)&u.y);
            float* dst = &KV[row * 64 + c4];
            dst[0] = f0.x; dst[1] = f0.y; dst[2] = f1.x; dst[3] = f1.y;
        }
        __syncthreads();
#pragma unroll 4
        for (int jj = 0; jj < 64; ++jj) {
            float4 vv = *(const float4*)&KV[jj * 64 + ttj];
            float p[4];
#pragma unroll
            for (int i = 0; i < 4; ++i) p[i] = sc[(ttq + i) * SCP + jt * 64 + jj];
#pragma unroll
            for (int i = 0; i < 4; ++i) {
                o[i][0] += p[i] * vv.x;
                o[i][1] += p[i] * vv.y;
                o[i][2] += p[i] * vv.z;
                o[i][3] += p[i] * vv.w;
            }
        }
    }
#pragma unroll
    for (int i = 0; i < 4; ++i) {
        int q = ttq + i;
        float il = invl[q];
        uint32_t h0 = pack_half2(o[i][0] * il, o[i][1] * il);
        uint32_t h1 = pack_half2(o[i][2] * il, o[i][3] * il);
        *(uint2*)&g_att[(size_t)(q0 + q) * D + qoff + ttj] = make_uint2(h0, h1);
    }
}

// ---------------- host ----------------
extern "C" void kernel_launch(void* const* d_in, const int* in_sizes, int n_in,
                              void* d_out, int out_size) {
    const int*   ids   = (const int*)  d_in[0];
    const float* emb   = (const float*)d_in[1];
    const float* pos   = (const float*)d_in[2];
    const float* wq    = (const float*)d_in[3];
    const float* bq    = (const float*)d_in[4];
    const float* wk    = (const float*)d_in[5];
    const float* bk    = (const float*)d_in[6];
    const float* wv    = (const float*)d_in[7];
    const float* bv    = (const float*)d_in[8];
    const float* wo    = (const float*)d_in[9];
    const float* bo    = (const float*)d_in[10];
    const float* w1    = (const float*)d_in[11];
    const float* b1    = (const float*)d_in[12];
    const float* w2    = (const float*)d_in[13];
    const float* b2    = (const float*)d_in[14];
    const float* ln1_g = (const float*)d_in[15];
    const float* ln1_b = (const float*)d_in[16];
    const float* ln2_g = (const float*)d_in[17];
    const float* ln2_b = (const float*)d_in[18];
    const float* out_g = (const float*)d_in[19];
    const float* out_b = (const float*)d_in[20];
    float* logits = (float*)d_out;

    float *x, *bqkv;
    __half *h, *qkv, *att, *ffn, *wT, *embT;
    cudaGetSymbolAddress((void**)&x,    g_x);
    cudaGetSymbolAddress((void**)&h,    g_h);
    cudaGetSymbolAddress((void**)&qkv,  g_qkv);
    cudaGetSymbolAddress((void**)&att,  g_att);
    cudaGetSymbolAddress((void**)&ffn,  g_ffn);
    cudaGetSymbolAddress((void**)&wT,   g_wT);
    cudaGetSymbolAddress((void**)&embT, g_embT);
    cudaGetSymbolAddress((void**)&bqkv, g_bqkv);

    const int GEMM_SM = NSTG * TILE_W * 2 * 4;                 // 81920 B
    const int ATTN_SM = (4096 + 4096 + 64 * SCP + 64) * 4;     // ~116 KB
    cudaFuncSetAttribute(mma_gemm<true,  true,  false, false>, cudaFuncAttributeMaxDynamicSharedMemorySize, GEMM_SM);
    cudaFuncSetAttribute(mma_gemm<false, true,  false, true >, cudaFuncAttributeMaxDynamicSharedMemorySize, GEMM_SM);
    cudaFuncSetAttribute(mma_gemm<true,  true,  true,  false>, cudaFuncAttributeMaxDynamicSharedMemorySize, GEMM_SM);
    cudaFuncSetAttribute(mma_gemm<false, false, false, false>, cudaFuncAttributeMaxDynamicSharedMemorySize, GEMM_SM);
    cudaFuncSetAttribute(attn_tiled, cudaFuncAttributeMaxDynamicSharedMemorySize, ATTN_SM);

    // ---- weight prep: transpose + fp16 convert ----
    dim3 tb(32, 8);
    for (int l = 0; l < NL; ++l) {
        __half* base = wT + (size_t)l * 12 * MB_ELT;
        transpose_half<<<dim3(D / 32,  D / 32),  tb>>>(wq + (size_t)l * D * D,  base + 0 * MB_ELT, D, D);
        transpose_half<<<dim3(D / 32,  D / 32),  tb>>>(wk + (size_t)l * D * D,  base + 1 * MB_ELT, D, D);
        transpose_half<<<dim3(D / 32,  D / 32),  tb>>>(wv + (size_t)l * D * D,  base + 2 * MB_ELT, D, D);
        transpose_half<<<dim3(D / 32,  D / 32),  tb>>>(wo + (size_t)l * D * D,  base + 3 * MB_ELT, D, D);
        transpose_half<<<dim3(DF / 32, D / 32),  tb>>>(w1 + (size_t)l * D * DF, base + 4 * MB_ELT, D, DF);
        transpose_half<<<dim3(D / 32,  DF / 32), tb>>>(w2 + (size_t)l * DF * D, base + 8 * MB_ELT, DF, D);
        concat_bias<<<(3 * D + 255) / 256, 256>>>(bq + l * D, bk + l * D, bv + l * D, bqkv + l * 3 * D);
    }
    {
        int n4 = VOCAB * D / 4;
        f2h_copy4<<<(n4 + 255) / 256, 256>>>((const float4*)emb, embT, n4);
    }

    // ---- forward ----
    embed_kernel<<<(S * D + 255) / 256, 256>>>(ids, emb, pos);

    for (int l = 0; l < NL; ++l) {
        __half* base = wT + (size_t)l * 12 * MB_ELT;

        ln_kernel<<<S, 256>>>(x, h, ln1_g + l * D, ln1_b + l * D);

        // qkv = h @ Wqkv^T + b   (N = 3072), half out
        mma_gemm<true, true, false, false><<<dim3(S / BM, 3 * D / BN), 256, GEMM_SM>>>(
            h, base + 0 * MB_ELT, bqkv + (size_t)l * 3 * D, nullptr, qkv, 3 * D, D);

        attn_tiled<<<dim3(S / TQ, H), 256, ATTN_SM>>>();

        // x = x + att @ wo^T + bo (fp32 out)
        mma_gemm<false, true, false, true><<<dim3(S / BM, D / BN), 256, GEMM_SM>>>(
            att, base + 3 * MB_ELT, bo + (size_t)l * D, x, x, D, D);

        ln_kernel<<<S, 256>>>(x, h, ln2_g + l * D, ln2_b + l * D);

        // ffn = gelu(h @ w1^T + b1), half out
        mma_gemm<true, true, true, false><<<dim3(S / BM, DF / BN), 256, GEMM_SM>>>(
            h, base + 4 * MB_ELT, b1 + (size_t)l * DF, nullptr, ffn, DF, D);

        // x = x + ffn @ w2^T + b2 (fp32 out)
        mma_gemm<false, true, false, true><<<dim3(S / BM, D / BN), 256, GEMM_SM>>>(
            ffn, base + 8 * MB_ELT, b2 + (size_t)l * D, x, x, D, DF);
    }

    ln_kernel<<<S, 256>>>(x, h, out_g, out_b);

    // logits = h @ emb^T (fp32 out)
    mma_gemm<false, false, false, false><<<dim3(S / BM, VOCAB / BN), 256, GEMM_SM>>>(
        h, embT, nullptr, nullptr, logits, VOCAB, D);
}

// round 6
// speedup vs baseline: 5.7507x; 1.0135x over previous
#include <cuda_runtime.h>
#include <cuda_fp16.h>
#include <math.h>
#include <stdint.h>

// ---------------- problem constants ----------------
#define S 2048
#define D 1024
#define H 16
#define HD 64
#define DF 4096
#define NL 2
#define VOCAB 32000
#define HALFW 128
#define ATT_SCALE 0.125f
#define LN_EPS 1e-5f
#define MB_ELT (1024*1024)

// ---------------- scratch (device globals) ----------------
__device__ float  g_x[S * D];               // residual stream (fp32)
__device__ __half g_h[S * D];               // LN output (GEMM A)
__device__ __half g_qkv[S * 3 * D];
__device__ __half g_att[S * D];
__device__ __half g_ffn[S * DF];
__device__ __half g_wT[NL * 12 * MB_ELT];   // per layer: qkvT(3M) woT(1M) w1T(4M) w2T(4M)
__device__ __half g_embT[VOCAB * D];
__device__ float  g_bqkv[NL * 3 * D];

// ---------------- helpers ----------------
__device__ __forceinline__ uint32_t smem_u32(const void* p) {
    uint32_t a;
    asm("{ .reg .u64 t; cvta.to.shared.u64 t, %1; cvt.u32.u64 %0, t; }" : "=r"(a) : "l"(p));
    return a;
}
__device__ __forceinline__ void cp16(uint32_t dst, const void* src) {
    asm volatile("cp.async.cg.shared.global [%0], [%1], 16;" :: "r"(dst), "l"(src));
}
__device__ __forceinline__ void cp_commit() {
    asm volatile("cp.async.commit_group;" ::: "memory");
}
template<int N>
__device__ __forceinline__ void cp_wait() {
    asm volatile("cp.async.wait_group %0;" :: "n"(N) : "memory");
}
__device__ __forceinline__ void ldsm_x4(uint32_t* r, uint32_t addr) {
    asm volatile("ldmatrix.sync.aligned.m8n8.x4.shared.b16 {%0,%1,%2,%3}, [%4];"
        : "=r"(r[0]), "=r"(r[1]), "=r"(r[2]), "=r"(r[3]) : "r"(addr));
}
__device__ __forceinline__ void mma_f16(float* c, const uint32_t* a, const uint32_t* b) {
    asm volatile(
        "mma.sync.aligned.m16n8k16.row.col.f32.f16.f16.f32 "
        "{%0,%1,%2,%3}, {%4,%5,%6,%7}, {%8,%9}, {%0,%1,%2,%3};"
        : "+f"(c[0]), "+f"(c[1]), "+f"(c[2]), "+f"(c[3])
        : "r"(a[0]), "r"(a[1]), "r"(a[2]), "r"(a[3]), "r"(b[0]), "r"(b[1]));
}
__device__ __forceinline__ float gelu_exact(float v) {
    return 0.5f * v * (1.0f + erff(v * 0.70710678118654752f));
}
__device__ __forceinline__ uint32_t pack_half2(float a, float b) {
    __half2 h = __floats2half2_rn(a, b);
    return *(uint32_t*)&h;
}

// ---------------- fp16 mma.sync GEMM: C[2048, N] = A[M,K] * B[N,K]^T ----------------
// BM=128, BNT template (128 or 256), BKT=32, 4-stage cp.async, ldmatrix, fp32 accum.
// BNT=256: 8 warps in 2x4 grid, 64x64 warp tiles (tensor-bound config).
// BNT=128: 8 warps in 4x2 grid, 32x64 warp tiles (better grid fill for small N).
#define BM 128
#define BKT 32
#define PADW 20                  // words per row: 16 data + 4 pad (conflict-free ldsm)
#define NSTG 4

template<int BNT, bool OUT_HALF, bool HAS_BIAS, bool DO_GELU, bool DO_RES>
__global__ __launch_bounds__(256, 1) void mma_gemm(
    const __half* __restrict__ A, const __half* __restrict__ B,
    const float* __restrict__ bias, const float* __restrict__ res,
    void* __restrict__ Cout, int N_total, int K_total)
{
    constexpr int MT = (BNT == 256) ? 4 : 2;           // 16-row A tiles per warp
    constexpr int STW = (BM + BNT) * PADW;             // words per stage

    extern __shared__ __align__(16) uint32_t smw[];

    const int tid = threadIdx.x;
    const int bm = blockIdx.x * BM;
    const int bn = blockIdx.y * BNT;
    const int wid = tid >> 5, lane = tid & 31;
    const int wm = (BNT == 256) ? (wid & 1) * 64 : (wid & 3) * 32;
    const int wn = (BNT == 256) ? (wid >> 1) * 64 : (wid >> 2) * 64;
    const int grp = lane >> 2, tig = lane & 3;

    // ldmatrix per-lane byte offsets (relative to A-tile / B-tile base)
    const uint32_t a_base = ((uint32_t)(wm + (lane & 15)) * PADW + ((lane >> 4) & 1) * 4) * 4;
    const uint32_t b_base = ((uint32_t)(wn + ((lane >> 4) & 1) * 8 + (lane & 7)) * PADW + ((lane >> 3) & 1) * 4) * 4;

    float acc[MT][8][4];
#pragma unroll
    for (int i = 0; i < MT; ++i)
#pragma unroll
        for (int j = 0; j < 8; ++j)
#pragma unroll
            for (int q = 0; q < 4; ++q) acc[i][j][q] = 0.f;

    const int nIter = K_total / BKT;

    // cp.async fill of one stage: A 512 chunks (16B), B BNT*4 chunks
    auto fill = [&](int st, int k0) {
        uint32_t* Ast = smw + st * STW;
        uint32_t* Bst = Ast + BM * PADW;
#pragma unroll
        for (int i = 0; i < 2; ++i) {
            int id = tid + i * 256;
            int row = id >> 2, c = id & 3;
            cp16(smem_u32(Ast + row * PADW + c * 4), A + (size_t)(bm + row) * K_total + k0 + c * 8);
        }
#pragma unroll
        for (int i = 0; i < BNT / 64; ++i) {
            int id = tid + i * 256;
            int row = id >> 2, c = id & 3;
            cp16(smem_u32(Bst + row * PADW + c * 4), B + (size_t)(bn + row) * K_total + k0 + c * 8);
        }
    };

#pragma unroll
    for (int s = 0; s < NSTG - 1; ++s) {
        fill(s, s * BKT);
        cp_commit();
    }

    for (int c = 0; c < nIter; ++c) {
        cp_wait<NSTG - 2>();
        __syncthreads();

        int nk = c + NSTG - 1;
        if (nk < nIter) fill(nk % NSTG, nk * BKT);
        cp_commit();

        const uint32_t sa = smem_u32(smw + (c % NSTG) * STW) + a_base;
        const uint32_t sb = smem_u32(smw + (c % NSTG) * STW + BM * PADW) + b_base;
#pragma unroll
        for (int ks = 0; ks < 2; ++ks) {
            uint32_t af[MT][4];
#pragma unroll
            for (int mt = 0; mt < MT; ++mt)
                ldsm_x4(af[mt], sa + (uint32_t)(mt * 16 * PADW * 4 + ks * 32));
            uint32_t bf[8][2];
#pragma unroll
            for (int p = 0; p < 4; ++p) {
                uint32_t r[4];
                ldsm_x4(r, sb + (uint32_t)(p * 16 * PADW * 4 + ks * 32));
                bf[2 * p][0] = r[0]; bf[2 * p][1] = r[1];
                bf[2 * p + 1][0] = r[2]; bf[2 * p + 1][1] = r[3];
            }
#pragma unroll
            for (int mt = 0; mt < MT; ++mt)
#pragma unroll
                for (int nt = 0; nt < 8; ++nt)
                    mma_f16(acc[mt][nt], af[mt], bf[nt]);
        }
    }

    // epilogue
#pragma unroll
    for (int mt = 0; mt < MT; ++mt) {
        const int r0 = bm + wm + mt * 16 + grp;
#pragma unroll
        for (int nt = 0; nt < 8; ++nt) {
            const int cn = bn + wn + nt * 8 + tig * 2;
#pragma unroll
            for (int hh = 0; hh < 2; ++hh) {
                const int row = r0 + hh * 8;
                float v0 = acc[mt][nt][hh * 2 + 0];
                float v1 = acc[mt][nt][hh * 2 + 1];
                if (HAS_BIAS) { v0 += __ldg(&bias[cn]); v1 += __ldg(&bias[cn + 1]); }
                if (DO_GELU) { v0 = gelu_exact(v0); v1 = gelu_exact(v1); }
                if (DO_RES) {
                    const float2 rv = *(const float2*)(res + (size_t)row * N_total + cn);
                    v0 += rv.x; v1 += rv.y;
                }
                if (OUT_HALF) {
                    uint32_t hv = pack_half2(v0, v1);
                    *(uint32_t*)((__half*)Cout + (size_t)row * N_total + cn) = hv;
                } else {
                    *(float2*)((float*)Cout + (size_t)row * N_total + cn) = make_float2(v0, v1);
                }
            }
        }
    }
}

// ---------------- small kernels ----------------
__global__ void embed_kernel(const int* __restrict__ ids,
                             const float* __restrict__ emb,
                             const float* __restrict__ pos) {
    int idx = blockIdx.x * blockDim.x + threadIdx.x;
    if (idx >= S * D) return;
    int s = idx >> 10;
    int d = idx & (D - 1);
    g_x[idx] = emb[(size_t)ids[s] * D + d] + pos[idx];
}

__global__ __launch_bounds__(256) void ln_kernel(const float* __restrict__ x,
                                                 __half* __restrict__ out,
                                                 const float* __restrict__ g,
                                                 const float* __restrict__ b) {
    __shared__ float rs[256], rs2[256];
    int row = blockIdx.x;
    int t = threadIdx.x;
    const float* xr = x + (size_t)row * D;
    float s = 0.f, s2 = 0.f;
#pragma unroll
    for (int i = t; i < D; i += 256) { float v = xr[i]; s += v; s2 += v * v; }
    rs[t] = s; rs2[t] = s2;
    __syncthreads();
    for (int off = 128; off > 0; off >>= 1) {
        if (t < off) { rs[t] += rs[t + off]; rs2[t] += rs2[t + off]; }
        __syncthreads();
    }
    float mu = rs[0] * (1.0f / D);
    float var = rs2[0] * (1.0f / D) - mu * mu;
    float inv = rsqrtf(var + LN_EPS);
    __half* orow = out + (size_t)row * D;
#pragma unroll
    for (int i = t; i < D; i += 256)
        orow[i] = __float2half_rn((xr[i] - mu) * inv * g[i] + b[i]);
}

// transpose fp32 -> half: out[C][R] = half(in[R][C]^T)
__global__ void transpose_half(const float* __restrict__ in, __half* __restrict__ out, int R, int C) {
    __shared__ float t[32][33];
    int c0 = blockIdx.x * 32, r0 = blockIdx.y * 32;
    int x = threadIdx.x, y = threadIdx.y;
#pragma unroll
    for (int i = y; i < 32; i += 8) t[i][x] = in[(size_t)(r0 + i) * C + c0 + x];
    __syncthreads();
#pragma unroll
    for (int i = y; i < 32; i += 8) out[(size_t)(c0 + i) * R + r0 + x] = __float2half_rn(t[x][i]);
}

__global__ void f2h_copy4(const float4* __restrict__ in, __half* __restrict__ out, int n4) {
    int i = blockIdx.x * blockDim.x + threadIdx.x;
    if (i >= n4) return;
    float4 v = in[i];
    uint32_t h0 = pack_half2(v.x, v.y);
    uint32_t h1 = pack_half2(v.z, v.w);
    *(uint2*)(out + (size_t)i * 4) = make_uint2(h0, h1);
}

__global__ void concat_bias(const float* __restrict__ bq, const float* __restrict__ bk,
                            const float* __restrict__ bv, float* __restrict__ out) {
    int i = blockIdx.x * blockDim.x + threadIdx.x;
    if (i >= 3 * D) return;
    out[i] = (i < D) ? bq[i] : (i < 2 * D) ? bk[i - D] : bv[i - 2 * D];
}

// ---------------- tiled local attention ----------------
#define TQ 64
#define JW 320
#define SCP 324

__global__ __launch_bounds__(256) void attn_tiled() {
    extern __shared__ __align__(16) float asm_[];
    float* Qs = asm_;                 // [64][64]
    float* KV = asm_ + 4096;          // [64][64]
    float* sc = asm_ + 8192;          // [64][SCP]
    float* invl = sc + 64 * SCP;      // [64]

    const int q0 = blockIdx.x * TQ;
    const int head = blockIdx.y;
    const int tid = threadIdx.x;
    const int RS = 3 * D;
    const int qoff = head * HD, koff = D + head * HD, voff = 2 * D + head * HD;
    const int jbase = q0 - HALFW;

    for (int i = tid; i < TQ * 16; i += 256) {
        int row = i >> 4, c4 = (i & 15) * 4;
        uint2 u = *(const uint2*)&g_qkv[(size_t)(q0 + row) * RS + qoff + c4];
        float2 f0 = __half22float2(*(__half2*)&u.x);
        float2 f1 = __half22float2(*(__half2*)&u.y);
        float* dst = &Qs[row * 64 + c4];
        dst[0] = f0.x; dst[1] = f0.y; dst[2] = f1.x; dst[3] = f1.y;
    }

    const int ttq = (tid >> 4) << 2;
    const int ttj = (tid & 15) << 2;

    // ---- scores ----
#pragma unroll 1
    for (int jt = 0; jt < 5; ++jt) {
        __syncthreads();
        for (int i = tid; i < TQ * 16; i += 256) {
            int row = i >> 4, c4 = (i & 15) * 4;
            int j = jbase + jt * 64 + row;
            j = min(max(j, 0), S - 1);
            uint2 u = *(const uint2*)&g_qkv[(size_t)j * RS + koff + c4];
            float2 f0 = __half22float2(*(__half2*)&u.x);
            float2 f1 = __half22float2(*(__half2*)&u.y);
            float* dst = &KV[row * 64 + c4];
            dst[0] = f0.x; dst[1] = f0.y; dst[2] = f1.x; dst[3] = f1.y;
        }
        __syncthreads();
        float a[4][4];
#pragma unroll
        for (int i = 0; i < 4; ++i)
#pragma unroll
            for (int j = 0; j < 4; ++j) a[i][j] = 0.f;
#pragma unroll
        for (int d = 0; d < 64; d += 4) {
            float4 qv[4], kv[4];
#pragma unroll
            for (int i = 0; i < 4; ++i) {
                qv[i] = *(const float4*)&Qs[(ttq + i) * 64 + d];
                kv[i] = *(const float4*)&KV[(ttj + i) * 64 + d];
            }
#pragma unroll
            for (int i = 0; i < 4; ++i)
#pragma unroll
                for (int j = 0; j < 4; ++j)
                    a[i][j] += qv[i].x * kv[j].x + qv[i].y * kv[j].y +
                               qv[i].z * kv[j].z + qv[i].w * kv[j].w;
        }
#pragma unroll
        for (int i = 0; i < 4; ++i)
#pragma unroll
            for (int j = 0; j < 4; ++j) {
                int qq = ttq + i;
                int jj = jt * 64 + ttj + j;
                int jg = jbase + jj;
                int qg = q0 + qq;
                bool ok = (jg >= 0) && (jg < S) && (abs(qg - jg) <= HALFW);
                sc[qq * SCP + jj] = ok ? a[i][j] * ATT_SCALE : -1e30f;
            }
    }
    __syncthreads();

    // ---- softmax ----
    const int wid = tid >> 5, lane = tid & 31;
    for (int r = 0; r < 8; ++r) {
        int q = wid * 8 + r;
        float m = -1e30f;
        for (int j = lane; j < JW; j += 32) m = fmaxf(m, sc[q * SCP + j]);
#pragma unroll
        for (int off = 16; off > 0; off >>= 1) m = fmaxf(m, __shfl_xor_sync(0xffffffffu, m, off));
        float s = 0.f;
        for (int j = lane; j < JW; j += 32) {
            float e = __expf(sc[q * SCP + j] - m);
            sc[q * SCP + j] = e;
            s += e;
        }
#pragma unroll
        for (int off = 16; off > 0; off >>= 1) s += __shfl_xor_sync(0xffffffffu, s, off);
        if (lane == 0) invl[q] = 1.0f / s;
    }
    __syncthreads();

    // ---- AV ----
    float o[4][4];
#pragma unroll
    for (int i = 0; i < 4; ++i)
#pragma unroll
        for (int j = 0; j < 4; ++j) o[i][j] = 0.f;
#pragma unroll 1
    for (int jt = 0; jt < 5; ++jt) {
        __syncthreads();
        for (int i = tid; i < TQ * 16; i += 256) {
            int row = i >> 4, c4 = (i & 15) * 4;
            int j = jbase + jt * 64 + row;
            j = min(max(j, 0), S - 1);
            uint2 u = *(const uint2*)&g_qkv[(size_t)j * RS + voff + c4];
            float2 f0 = __half22float2(*(__half2*)&u.x);
            float2 f1 = __half22float2(*(__half2*)&u.y);
            float* dst = &KV[row * 64 + c4];
            dst[0] = f0.x; dst[1] = f0.y; dst[2] = f1.x; dst[3] = f1.y;
        }
        __syncthreads();
#pragma unroll 4
        for (int jj = 0; jj < 64; ++jj) {
            float4 vv = *(const float4*)&KV[jj * 64 + ttj];
            float p[4];
#pragma unroll
            for (int i = 0; i < 4; ++i) p[i] = sc[(ttq + i) * SCP + jt * 64 + jj];
#pragma unroll
            for (int i = 0; i < 4; ++i) {
                o[i][0] += p[i] * vv.x;
                o[i][1] += p[i] * vv.y;
                o[i][2] += p[i] * vv.z;
                o[i][3] += p[i] * vv.w;
            }
        }
    }
#pragma unroll
    for (int i = 0; i < 4; ++i) {
        int q = ttq + i;
        float il = invl[q];
        uint32_t h0 = pack_half2(o[i][0] * il, o[i][1] * il);
        uint32_t h1 = pack_half2(o[i][2] * il, o[i][3] * il);
        *(uint2*)&g_att[(size_t)(q0 + q) * D + qoff + ttj] = make_uint2(h0, h1);
    }
}

// ---------------- host ----------------
extern "C" void kernel_launch(void* const* d_in, const int* in_sizes, int n_in,
                              void* d_out, int out_size) {
    const int*   ids   = (const int*)  d_in[0];
    const float* emb   = (const float*)d_in[1];
    const float* pos   = (const float*)d_in[2];
    const float* wq    = (const float*)d_in[3];
    const float* bq    = (const float*)d_in[4];
    const float* wk    = (const float*)d_in[5];
    const float* bk    = (const float*)d_in[6];
    const float* wv    = (const float*)d_in[7];
    const float* bv    = (const float*)d_in[8];
    const float* wo    = (const float*)d_in[9];
    const float* bo    = (const float*)d_in[10];
    const float* w1    = (const float*)d_in[11];
    const float* b1    = (const float*)d_in[12];
    const float* w2    = (const float*)d_in[13];
    const float* b2    = (const float*)d_in[14];
    const float* ln1_g = (const float*)d_in[15];
    const float* ln1_b = (const float*)d_in[16];
    const float* ln2_g = (const float*)d_in[17];
    const float* ln2_b = (const float*)d_in[18];
    const float* out_g = (const float*)d_in[19];
    const float* out_b = (const float*)d_in[20];
    float* logits = (float*)d_out;

    float *x, *bqkv;
    __half *h, *qkv, *att, *ffn, *wT, *embT;
    cudaGetSymbolAddress((void**)&x,    g_x);
    cudaGetSymbolAddress((void**)&h,    g_h);
    cudaGetSymbolAddress((void**)&qkv,  g_qkv);
    cudaGetSymbolAddress((void**)&att,  g_att);
    cudaGetSymbolAddress((void**)&ffn,  g_ffn);
    cudaGetSymbolAddress((void**)&wT,   g_wT);
    cudaGetSymbolAddress((void**)&embT, g_embT);
    cudaGetSymbolAddress((void**)&bqkv, g_bqkv);

    const int SM256 = (BM + 256) * PADW * 4 * NSTG;            // 122880 B
    const int SM128 = (BM + 128) * PADW * 4 * NSTG;            // 81920 B
    const int ATTN_SM = (4096 + 4096 + 64 * SCP + 64) * 4;     // ~116 KB
    cudaFuncSetAttribute(mma_gemm<256, true,  true,  false, false>, cudaFuncAttributeMaxDynamicSharedMemorySize, SM256);
    cudaFuncSetAttribute(mma_gemm<128, false, true,  false, true >, cudaFuncAttributeMaxDynamicSharedMemorySize, SM128);
    cudaFuncSetAttribute(mma_gemm<256, true,  true,  true,  false>, cudaFuncAttributeMaxDynamicSharedMemorySize, SM256);
    cudaFuncSetAttribute(mma_gemm<256, false, false, false, false>, cudaFuncAttributeMaxDynamicSharedMemorySize, SM256);
    cudaFuncSetAttribute(attn_tiled, cudaFuncAttributeMaxDynamicSharedMemorySize, ATTN_SM);

    // ---- weight prep: transpose + fp16 convert ----
    dim3 tb(32, 8);
    for (int l = 0; l < NL; ++l) {
        __half* base = wT + (size_t)l * 12 * MB_ELT;
        transpose_half<<<dim3(D / 32,  D / 32),  tb>>>(wq + (size_t)l * D * D,  base + 0 * MB_ELT, D, D);
        transpose_half<<<dim3(D / 32,  D / 32),  tb>>>(wk + (size_t)l * D * D,  base + 1 * MB_ELT, D, D);
        transpose_half<<<dim3(D / 32,  D / 32),  tb>>>(wv + (size_t)l * D * D,  base + 2 * MB_ELT, D, D);
        transpose_half<<<dim3(D / 32,  D / 32),  tb>>>(wo + (size_t)l * D * D,  base + 3 * MB_ELT, D, D);
        transpose_half<<<dim3(DF / 32, D / 32),  tb>>>(w1 + (size_t)l * D * DF, base + 4 * MB_ELT, D, DF);
        transpose_half<<<dim3(D / 32,  DF / 32), tb>>>(w2 + (size_t)l * DF * D, base + 8 * MB_ELT, DF, D);
        concat_bias<<<(3 * D + 255) / 256, 256>>>(bq + l * D, bk + l * D, bv + l * D, bqkv + l * 3 * D);
    }
    {
        int n4 = VOCAB * D / 4;
        f2h_copy4<<<(n4 + 255) / 256, 256>>>((const float4*)emb, embT, n4);
    }

    // ---- forward ----
    embed_kernel<<<(S * D + 255) / 256, 256>>>(ids, emb, pos);

    for (int l = 0; l < NL; ++l) {
        __half* base = wT + (size_t)l * 12 * MB_ELT;

        ln_kernel<<<S, 256>>>(x, h, ln1_g + l * D, ln1_b + l * D);

        // qkv = h @ Wqkv^T + b   (N = 3072), half out
        mma_gemm<256, true, true, false, false><<<dim3(S / BM, 3 * D / 256), 256, SM256>>>(
            h, base + 0 * MB_ELT, bqkv + (size_t)l * 3 * D, nullptr, qkv, 3 * D, D);

        attn_tiled<<<dim3(S / TQ, H), 256, ATTN_SM>>>();

        // x = x + att @ wo^T + bo (fp32 out)
        mma_gemm<128, false, true, false, true><<<dim3(S / BM, D / 128), 256, SM128>>>(
            att, base + 3 * MB_ELT, bo + (size_t)l * D, x, x, D, D);

        ln_kernel<<<S, 256>>>(x, h, ln2_g + l * D, ln2_b + l * D);

        // ffn = gelu(h @ w1^T + b1), half out
        mma_gemm<256, true, true, true, false><<<dim3(S / BM, DF / 256), 256, SM256>>>(
            h, base + 4 * MB_ELT, b1 + (size_t)l * DF, nullptr, ffn, DF, D);

        // x = x + ffn @ w2^T + b2 (fp32 out)
        mma_gemm<128, false, true, false, true><<<dim3(S / BM, D / 128), 256, SM128>>>(
            ffn, base + 8 * MB_ELT, b2 + (size_t)l * D, x, x, D, DF);
    }

    ln_kernel<<<S, 256>>>(x, h, out_g, out_b);

    // logits = h @ emb^T (fp32 out)
    mma_gemm<256, false, false, false, false><<<dim3(S / BM, VOCAB / 256), 256, SM256>>>(
        h, embT, nullptr, nullptr, logits, VOCAB, D);
}

// round 7
// speedup vs baseline: 6.2970x; 1.0950x over previous
#include <cuda_runtime.h>
#include <cuda_fp16.h>
#include <math.h>
#include <stdint.h>

// ---------------- problem constants ----------------
#define S 2048
#define D 1024
#define H 16
#define HD 64
#define DF 4096
#define NL 2
#define VOCAB 32000
#define HALFW 128
#define ATT_SCALE 0.125f
#define LN_EPS 1e-5f
#define MB_ELT (1024*1024)

// ---------------- scratch (device globals) ----------------
__device__ float  g_x[S * D];               // residual stream (fp32)
__device__ __half g_h[S * D];               // LN output (GEMM A)
__device__ __half g_qkv[S * 3 * D];
__device__ __half g_att[S * D];
__device__ __half g_ffn[S * DF];
__device__ __half g_wT[NL * 12 * MB_ELT];   // per layer: qkvT(3M) woT(1M) w1T(4M) w2T(4M)
__device__ __half g_embT[VOCAB * D];
__device__ float  g_bqkv[NL * 3 * D];

// ---------------- helpers ----------------
__device__ __forceinline__ uint32_t smem_u32(const void* p) {
    uint32_t a;
    asm("{ .reg .u64 t; cvta.to.shared.u64 t, %1; cvt.u32.u64 %0, t; }" : "=r"(a) : "l"(p));
    return a;
}
__device__ __forceinline__ void cp16(uint32_t dst, const void* src) {
    asm volatile("cp.async.cg.shared.global [%0], [%1], 16;" :: "r"(dst), "l"(src));
}
__device__ __forceinline__ void cp_commit() {
    asm volatile("cp.async.commit_group;" ::: "memory");
}
template<int N>
__device__ __forceinline__ void cp_wait() {
    asm volatile("cp.async.wait_group %0;" :: "n"(N) : "memory");
}
__device__ __forceinline__ void ldsm_x4(uint32_t* r, uint32_t addr) {
    asm volatile("ldmatrix.sync.aligned.m8n8.x4.shared.b16 {%0,%1,%2,%3}, [%4];"
        : "=r"(r[0]), "=r"(r[1]), "=r"(r[2]), "=r"(r[3]) : "r"(addr));
}
__device__ __forceinline__ void mma_f16(float* c, const uint32_t* a, const uint32_t* b) {
    asm volatile(
        "mma.sync.aligned.m16n8k16.row.col.f32.f16.f16.f32 "
        "{%0,%1,%2,%3}, {%4,%5,%6,%7}, {%8,%9}, {%0,%1,%2,%3};"
        : "+f"(c[0]), "+f"(c[1]), "+f"(c[2]), "+f"(c[3])
        : "r"(a[0]), "r"(a[1]), "r"(a[2]), "r"(a[3]), "r"(b[0]), "r"(b[1]));
}
__device__ __forceinline__ float gelu_exact(float v) {
    return 0.5f * v * (1.0f + erff(v * 0.70710678118654752f));
}
__device__ __forceinline__ uint32_t pack_half2(float a, float b) {
    __half2 h = __floats2half2_rn(a, b);
    return *(uint32_t*)&h;
}

// ---------------- fp16 mma.sync GEMM: C[2048, N] = A[M,K] * B[N,K]^T ----------------
// 128x128x32 tiles, 4-stage cp.async, ldmatrix, fp32 accum, 2 CTAs/SM.
#define BM 128
#define BNT 128
#define BKT 32
#define PADW 20                  // words per row: 16 data + 4 pad (conflict-free ldsm)
#define NSTG 4
#define STW ((BM + BNT) * PADW)  // words per stage

template<bool OUT_HALF, bool HAS_BIAS, bool DO_GELU, bool DO_RES>
__global__ __launch_bounds__(256, 2) void mma_gemm(
    const __half* __restrict__ A, const __half* __restrict__ B,
    const float* __restrict__ bias, const float* __restrict__ res,
    void* __restrict__ Cout, int N_total, int K_total)
{
    extern __shared__ __align__(16) uint32_t smw[];

    const int tid = threadIdx.x;
    const int bm = blockIdx.x * BM;
    const int bn = blockIdx.y * BNT;
    const int wid = tid >> 5, lane = tid & 31;
    const int wm = (wid & 3) * 32;            // 4x2 warp grid: 32x64 per warp
    const int wn = (wid >> 2) * 64;
    const int grp = lane >> 2, tig = lane & 3;

    const uint32_t a_base = ((uint32_t)(wm + (lane & 15)) * PADW + ((lane >> 4) & 1) * 4) * 4;
    const uint32_t b_base = ((uint32_t)(wn + ((lane >> 4) & 1) * 8 + (lane & 7)) * PADW + ((lane >> 3) & 1) * 4) * 4;

    float acc[2][8][4];
#pragma unroll
    for (int i = 0; i < 2; ++i)
#pragma unroll
        for (int j = 0; j < 8; ++j)
#pragma unroll
            for (int q = 0; q < 4; ++q) acc[i][j][q] = 0.f;

    const int nIter = K_total / BKT;

    auto fill = [&](int st, int k0) {
        uint32_t* Ast = smw + st * STW;
        uint32_t* Bst = Ast + BM * PADW;
#pragma unroll
        for (int i = 0; i < 2; ++i) {
            int id = tid + i * 256;
            int row = id >> 2, c = id & 3;
            cp16(smem_u32(Ast + row * PADW + c * 4), A + (size_t)(bm + row) * K_total + k0 + c * 8);
        }
#pragma unroll
        for (int i = 0; i < 2; ++i) {
            int id = tid + i * 256;
            int row = id >> 2, c = id & 3;
            cp16(smem_u32(Bst + row * PADW + c * 4), B + (size_t)(bn + row) * K_total + k0 + c * 8);
        }
    };

#pragma unroll
    for (int s = 0; s < NSTG - 1; ++s) {
        fill(s, s * BKT);
        cp_commit();
    }

    for (int c = 0; c < nIter; ++c) {
        cp_wait<NSTG - 2>();
        __syncthreads();

        int nk = c + NSTG - 1;
        if (nk < nIter) fill(nk % NSTG, nk * BKT);
        cp_commit();

        const uint32_t sa = smem_u32(smw + (c % NSTG) * STW) + a_base;
        const uint32_t sb = smem_u32(smw + (c % NSTG) * STW + BM * PADW) + b_base;
#pragma unroll
        for (int ks = 0; ks < 2; ++ks) {
            uint32_t af[2][4];
#pragma unroll
            for (int mt = 0; mt < 2; ++mt)
                ldsm_x4(af[mt], sa + (uint32_t)(mt * 16 * PADW * 4 + ks * 32));
            uint32_t bf[8][2];
#pragma unroll
            for (int p = 0; p < 4; ++p) {
                uint32_t r[4];
                ldsm_x4(r, sb + (uint32_t)(p * 16 * PADW * 4 + ks * 32));
                bf[2 * p][0] = r[0]; bf[2 * p][1] = r[1];
                bf[2 * p + 1][0] = r[2]; bf[2 * p + 1][1] = r[3];
            }
#pragma unroll
            for (int mt = 0; mt < 2; ++mt)
#pragma unroll
                for (int nt = 0; nt < 8; ++nt)
                    mma_f16(acc[mt][nt], af[mt], bf[nt]);
        }
    }

    // epilogue
#pragma unroll
    for (int mt = 0; mt < 2; ++mt) {
        const int r0 = bm + wm + mt * 16 + grp;
#pragma unroll
        for (int nt = 0; nt < 8; ++nt) {
            const int cn = bn + wn + nt * 8 + tig * 2;
#pragma unroll
            for (int hh = 0; hh < 2; ++hh) {
                const int row = r0 + hh * 8;
                float v0 = acc[mt][nt][hh * 2 + 0];
                float v1 = acc[mt][nt][hh * 2 + 1];
                if (HAS_BIAS) { v0 += __ldg(&bias[cn]); v1 += __ldg(&bias[cn + 1]); }
                if (DO_GELU) { v0 = gelu_exact(v0); v1 = gelu_exact(v1); }
                if (DO_RES) {
                    const float2 rv = *(const float2*)(res + (size_t)row * N_total + cn);
                    v0 += rv.x; v1 += rv.y;
                }
                if (OUT_HALF) {
                    uint32_t hv = pack_half2(v0, v1);
                    *(uint32_t*)((__half*)Cout + (size_t)row * N_total + cn) = hv;
                } else {
                    *(float2*)((float*)Cout + (size_t)row * N_total + cn) = make_float2(v0, v1);
                }
            }
        }
    }
}

// ---------------- small kernels ----------------
__global__ void embed_kernel(const int* __restrict__ ids,
                             const float* __restrict__ emb,
                             const float* __restrict__ pos) {
    int idx = blockIdx.x * blockDim.x + threadIdx.x;
    if (idx >= S * D) return;
    int s = idx >> 10;
    int d = idx & (D - 1);
    g_x[idx] = emb[(size_t)ids[s] * D + d] + pos[idx];
}

__global__ __launch_bounds__(256) void ln_kernel(const float* __restrict__ x,
                                                 __half* __restrict__ out,
                                                 const float* __restrict__ g,
                                                 const float* __restrict__ b) {
    __shared__ float rs[256], rs2[256];
    int row = blockIdx.x;
    int t = threadIdx.x;
    const float* xr = x + (size_t)row * D;
    float s = 0.f, s2 = 0.f;
#pragma unroll
    for (int i = t; i < D; i += 256) { float v = xr[i]; s += v; s2 += v * v; }
    rs[t] = s; rs2[t] = s2;
    __syncthreads();
    for (int off = 128; off > 0; off >>= 1) {
        if (t < off) { rs[t] += rs[t + off]; rs2[t] += rs2[t + off]; }
        __syncthreads();
    }
    float mu = rs[0] * (1.0f / D);
    float var = rs2[0] * (1.0f / D) - mu * mu;
    float inv = rsqrtf(var + LN_EPS);
    __half* orow = out + (size_t)row * D;
#pragma unroll
    for (int i = t; i < D; i += 256)
        orow[i] = __float2half_rn((xr[i] - mu) * inv * g[i] + b[i]);
}

// transpose fp32 -> half: out[C][R] = half(in[R][C]^T)
__global__ void transpose_half(const float* __restrict__ in, __half* __restrict__ out, int R, int C) {
    __shared__ float t[32][33];
    int c0 = blockIdx.x * 32, r0 = blockIdx.y * 32;
    int x = threadIdx.x, y = threadIdx.y;
#pragma unroll
    for (int i = y; i < 32; i += 8) t[i][x] = in[(size_t)(r0 + i) * C + c0 + x];
    __syncthreads();
#pragma unroll
    for (int i = y; i < 32; i += 8) out[(size_t)(c0 + i) * R + r0 + x] = __float2half_rn(t[x][i]);
}

__global__ void f2h_copy4(const float4* __restrict__ in, __half* __restrict__ out, int n4) {
    int i = blockIdx.x * blockDim.x + threadIdx.x;
    if (i >= n4) return;
    float4 v = in[i];
    uint32_t h0 = pack_half2(v.x, v.y);
    uint32_t h1 = pack_half2(v.z, v.w);
    *(uint2*)(out + (size_t)i * 4) = make_uint2(h0, h1);
}

__global__ void concat_bias(const float* __restrict__ bq, const float* __restrict__ bk,
                            const float* __restrict__ bv, float* __restrict__ out) {
    int i = blockIdx.x * blockDim.x + threadIdx.x;
    if (i >= 3 * D) return;
    out[i] = (i < D) ? bq[i] : (i < 2 * D) ? bk[i - D] : bv[i - 2 * D];
}

// ---------------- tiled local attention ----------------
#define TQ 64
#define JW 320
#define SCP 324

__global__ __launch_bounds__(256) void attn_tiled() {
    extern __shared__ __align__(16) float asm_[];
    float* Qs = asm_;                 // [64][64]
    float* KV = asm_ + 4096;          // [64][64]
    float* sc = asm_ + 8192;          // [64][SCP]
    float* invl = sc + 64 * SCP;      // [64]

    const int q0 = blockIdx.x * TQ;
    const int head = blockIdx.y;
    const int tid = threadIdx.x;
    const int RS = 3 * D;
    const int qoff = head * HD, koff = D + head * HD, voff = 2 * D + head * HD;
    const int jbase = q0 - HALFW;

    for (int i = tid; i < TQ * 16; i += 256) {
        int row = i >> 4, c4 = (i & 15) * 4;
        uint2 u = *(const uint2*)&g_qkv[(size_t)(q0 + row) * RS + qoff + c4];
        float2 f0 = __half22float2(*(__half2*)&u.x);
        float2 f1 = __half22float2(*(__half2*)&u.y);
        float* dst = &Qs[row * 64 + c4];
        dst[0] = f0.x; dst[1] = f0.y; dst[2] = f1.x; dst[3] = f1.y;
    }

    const int ttq = (tid >> 4) << 2;
    const int ttj = (tid & 15) << 2;

    // ---- scores ----
#pragma unroll 1
    for (int jt = 0; jt < 5; ++jt) {
        __syncthreads();
        for (int i = tid; i < TQ * 16; i += 256) {
            int row = i >> 4, c4 = (i & 15) * 4;
            int j = jbase + jt * 64 + row;
            j = min(max(j, 0), S - 1);
            uint2 u = *(const uint2*)&g_qkv[(size_t)j * RS + koff + c4];
            float2 f0 = __half22float2(*(__half2*)&u.x);
            float2 f1 = __half22float2(*(__half2*)&u.y);
            float* dst = &KV[row * 64 + c4];
            dst[0] = f0.x; dst[1] = f0.y; dst[2] = f1.x; dst[3] = f1.y;
        }
        __syncthreads();
        float a[4][4];
#pragma unroll
        for (int i = 0; i < 4; ++i)
#pragma unroll
            for (int j = 0; j < 4; ++j) a[i][j] = 0.f;
#pragma unroll
        for (int d = 0; d < 64; d += 4) {
            float4 qv[4], kv[4];
#pragma unroll
            for (int i = 0; i < 4; ++i) {
                qv[i] = *(const float4*)&Qs[(ttq + i) * 64 + d];
                kv[i] = *(const float4*)&KV[(ttj + i) * 64 + d];
            }
#pragma unroll
            for (int i = 0; i < 4; ++i)
#pragma unroll
                for (int j = 0; j < 4; ++j)
                    a[i][j] += qv[i].x * kv[j].x + qv[i].y * kv[j].y +
                               qv[i].z * kv[j].z + qv[i].w * kv[j].w;
        }
#pragma unroll
        for (int i = 0; i < 4; ++i)
#pragma unroll
            for (int j = 0; j < 4; ++j) {
                int qq = ttq + i;
                int jj = jt * 64 + ttj + j;
                int jg = jbase + jj;
                int qg = q0 + qq;
                bool ok = (jg >= 0) && (jg < S) && (abs(qg - jg) <= HALFW);
                sc[qq * SCP + jj] = ok ? a[i][j] * ATT_SCALE : -1e30f;
            }
    }
    __syncthreads();

    // ---- softmax ----
    const int wid = tid >> 5, lane = tid & 31;
    for (int r = 0; r < 8; ++r) {
        int q = wid * 8 + r;
        float m = -1e30f;
        for (int j = lane; j < JW; j += 32) m = fmaxf(m, sc[q * SCP + j]);
#pragma unroll
        for (int off = 16; off > 0; off >>= 1) m = fmaxf(m, __shfl_xor_sync(0xffffffffu, m, off));
        float s = 0.f;
        for (int j = lane; j < JW; j += 32) {
            float e = __expf(sc[q * SCP + j] - m);
            sc[q * SCP + j] = e;
            s += e;
        }
#pragma unroll
        for (int off = 16; off > 0; off >>= 1) s += __shfl_xor_sync(0xffffffffu, s, off);
        if (lane == 0) invl[q] = 1.0f / s;
    }
    __syncthreads();

    // ---- AV ----
    float o[4][4];
#pragma unroll
    for (int i = 0; i < 4; ++i)
#pragma unroll
        for (int j = 0; j < 4; ++j) o[i][j] = 0.f;
#pragma unroll 1
    for (int jt = 0; jt < 5; ++jt) {
        __syncthreads();
        for (int i = tid; i < TQ * 16; i += 256) {
            int row = i >> 4, c4 = (i & 15) * 4;
            int j = jbase + jt * 64 + row;
            j = min(max(j, 0), S - 1);
            uint2 u = *(const uint2*)&g_qkv[(size_t)j * RS + voff + c4];
            float2 f0 = __half22float2(*(__half2*)&u.x);
            float2 f1 = __half22float2(*(__half2*)&u.y);
            float* dst = &KV[row * 64 + c4];
            dst[0] = f0.x; dst[1] = f0.y; dst[2] = f1.x; dst[3] = f1.y;
        }
        __syncthreads();
#pragma unroll 4
        for (int jj = 0; jj < 64; ++jj) {
            float4 vv = *(const float4*)&KV[jj * 64 + ttj];
            float p[4];
#pragma unroll
            for (int i = 0; i < 4; ++i) p[i] = sc[(ttq + i) * SCP + jt * 64 + jj];
#pragma unroll
            for (int i = 0; i < 4; ++i) {
                o[i][0] += p[i] * vv.x;
                o[i][1] += p[i] * vv.y;
                o[i][2] += p[i] * vv.z;
                o[i][3] += p[i] * vv.w;
            }
        }
    }
#pragma unroll
    for (int i = 0; i < 4; ++i) {
        int q = ttq + i;
        float il = invl[q];
        uint32_t h0 = pack_half2(o[i][0] * il, o[i][1] * il);
        uint32_t h1 = pack_half2(o[i][2] * il, o[i][3] * il);
        *(uint2*)&g_att[(size_t)(q0 + q) * D + qoff + ttj] = make_uint2(h0, h1);
    }
}

// ---------------- host ----------------
extern "C" void kernel_launch(void* const* d_in, const int* in_sizes, int n_in,
                              void* d_out, int out_size) {
    const int*   ids   = (const int*)  d_in[0];
    const float* emb   = (const float*)d_in[1];
    const float* pos   = (const float*)d_in[2];
    const float* wq    = (const float*)d_in[3];
    const float* bq    = (const float*)d_in[4];
    const float* wk    = (const float*)d_in[5];
    const float* bk    = (const float*)d_in[6];
    const float* wv    = (const float*)d_in[7];
    const float* bv    = (const float*)d_in[8];
    const float* wo    = (const float*)d_in[9];
    const float* bo    = (const float*)d_in[10];
    const float* w1    = (const float*)d_in[11];
    const float* b1    = (const float*)d_in[12];
    const float* w2    = (const float*)d_in[13];
    const float* b2    = (const float*)d_in[14];
    const float* ln1_g = (const float*)d_in[15];
    const float* ln1_b = (const float*)d_in[16];
    const float* ln2_g = (const float*)d_in[17];
    const float* ln2_b = (const float*)d_in[18];
    const float* out_g = (const float*)d_in[19];
    const float* out_b = (const float*)d_in[20];
    float* logits = (float*)d_out;

    float *x, *bqkv;
    __half *h, *qkv, *att, *ffn, *wT, *embT;
    cudaGetSymbolAddress((void**)&x,    g_x);
    cudaGetSymbolAddress((void**)&h,    g_h);
    cudaGetSymbolAddress((void**)&qkv,  g_qkv);
    cudaGetSymbolAddress((void**)&att,  g_att);
    cudaGetSymbolAddress((void**)&ffn,  g_ffn);
    cudaGetSymbolAddress((void**)&wT,   g_wT);
    cudaGetSymbolAddress((void**)&embT, g_embT);
    cudaGetSymbolAddress((void**)&bqkv, g_bqkv);

    const int GEMM_SM = STW * 4 * NSTG;                        // 81920 B
    const int ATTN_SM = (4096 + 4096 + 64 * SCP + 64) * 4;     // ~116 KB
    cudaFuncSetAttribute(mma_gemm<true,  true,  false, false>, cudaFuncAttributeMaxDynamicSharedMemorySize, GEMM_SM);
    cudaFuncSetAttribute(mma_gemm<false, true,  false, true >, cudaFuncAttributeMaxDynamicSharedMemorySize, GEMM_SM);
    cudaFuncSetAttribute(mma_gemm<true,  true,  true,  false>, cudaFuncAttributeMaxDynamicSharedMemorySize, GEMM_SM);
    cudaFuncSetAttribute(mma_gemm<false, false, false, false>, cudaFuncAttributeMaxDynamicSharedMemorySize, GEMM_SM);
    cudaFuncSetAttribute(attn_tiled, cudaFuncAttributeMaxDynamicSharedMemorySize, ATTN_SM);

    // ---- weight prep: transpose + fp16 convert ----
    dim3 tb(32, 8);
    for (int l = 0; l < NL; ++l) {
        __half* base = wT + (size_t)l * 12 * MB_ELT;
        transpose_half<<<dim3(D / 32,  D / 32),  tb>>>(wq + (size_t)l * D * D,  base + 0 * MB_ELT, D, D);
        transpose_half<<<dim3(D / 32,  D / 32),  tb>>>(wk + (size_t)l * D * D,  base + 1 * MB_ELT, D, D);
        transpose_half<<<dim3(D / 32,  D / 32),  tb>>>(wv + (size_t)l * D * D,  base + 2 * MB_ELT, D, D);
        transpose_half<<<dim3(D / 32,  D / 32),  tb>>>(wo + (size_t)l * D * D,  base + 3 * MB_ELT, D, D);
        transpose_half<<<dim3(DF / 32, D / 32),  tb>>>(w1 + (size_t)l * D * DF, base + 4 * MB_ELT, D, DF);
        transpose_half<<<dim3(D / 32,  DF / 32), tb>>>(w2 + (size_t)l * DF * D, base + 8 * MB_ELT, DF, D);
        concat_bias<<<(3 * D + 255) / 256, 256>>>(bq + l * D, bk + l * D, bv + l * D, bqkv + l * 3 * D);
    }
    {
        int n4 = VOCAB * D / 4;
        f2h_copy4<<<(n4 + 255) / 256, 256>>>((const float4*)emb, embT, n4);
    }

    // ---- forward ----
    embed_kernel<<<(S * D + 255) / 256, 256>>>(ids, emb, pos);

    for (int l = 0; l < NL; ++l) {
        __half* base = wT + (size_t)l * 12 * MB_ELT;

        ln_kernel<<<S, 256>>>(x, h, ln1_g + l * D, ln1_b + l * D);

        // qkv = h @ Wqkv^T + b   (N = 3072), half out
        mma_gemm<true, true, false, false><<<dim3(S / BM, 3 * D / BNT), 256, GEMM_SM>>>(
            h, base + 0 * MB_ELT, bqkv + (size_t)l * 3 * D, nullptr, qkv, 3 * D, D);

        attn_tiled<<<dim3(S / TQ, H), 256, ATTN_SM>>>();

        // x = x + att @ wo^T + bo (fp32 out)
        mma_gemm<false, true, false, true><<<dim3(S / BM, D / BNT), 256, GEMM_SM>>>(
            att, base + 3 * MB_ELT, bo + (size_t)l * D, x, x, D, D);

        ln_kernel<<<S, 256>>>(x, h, ln2_g + l * D, ln2_b + l * D);

        // ffn = gelu(h @ w1^T + b1), half out
        mma_gemm<true, true, true, false><<<dim3(S / BM, DF / BNT), 256, GEMM_SM>>>(
            h, base + 4 * MB_ELT, b1 + (size_t)l * DF, nullptr, ffn, DF, D);

        // x = x + ffn @ w2^T + b2 (fp32 out)
        mma_gemm<false, true, false, true><<<dim3(S / BM, D / BNT), 256, GEMM_SM>>>(
            ffn, base + 8 * MB_ELT, b2 + (size_t)l * D, x, x, D, DF);
    }

    ln_kernel<<<S, 256>>>(x, h, out_g, out_b);

    // logits = h @ emb^T (fp32 out)
    mma_gemm<false, false, false, false><<<dim3(S / BM, VOCAB / BNT), 256, GEMM_SM>>>(
        h, embT, nullptr, nullptr, logits, VOCAB, D);
}

// round 8
// speedup vs baseline: 6.4742x; 1.0281x over previous
#include <cuda_runtime.h>
#include <cuda_fp16.h>
#include <math.h>
#include <stdint.h>

// ---------------- problem constants ----------------
#define S 2048
#define D 1024
#define H 16
#define HD 64
#define DF 4096
#define NL 2
#define VOCAB 32000
#define HALFW 128
#define ATT_SCALE 0.125f
#define LN_EPS 1e-5f
#define MB_ELT (1024*1024)

// ---------------- scratch (device globals) ----------------
__device__ float  g_x[S * D];               // residual stream (fp32)
__device__ __half g_h[S * D];               // LN output (GEMM A)
__device__ __half g_qkv[S * 3 * D];
__device__ __half g_att[S * D];
__device__ __half g_ffn[S * DF];
__device__ __half g_wT[NL * 12 * MB_ELT];   // per layer: qkvT(3M) woT(1M) w1T(4M) w2T(4M)
__device__ __half g_embT[VOCAB * D];
__device__ float  g_bqkv[NL * 3 * D];

// ---------------- helpers ----------------
__device__ __forceinline__ uint32_t smem_u32(const void* p) {
    uint32_t a;
    asm("{ .reg .u64 t; cvta.to.shared.u64 t, %1; cvt.u32.u64 %0, t; }" : "=r"(a) : "l"(p));
    return a;
}
__device__ __forceinline__ void cp16(uint32_t dst, const void* src) {
    asm volatile("cp.async.cg.shared.global [%0], [%1], 16;" :: "r"(dst), "l"(src));
}
__device__ __forceinline__ void cp_commit() {
    asm volatile("cp.async.commit_group;" ::: "memory");
}
template<int N>
__device__ __forceinline__ void cp_wait() {
    asm volatile("cp.async.wait_group %0;" :: "n"(N) : "memory");
}
__device__ __forceinline__ void ldsm_x4(uint32_t* r, uint32_t addr) {
    asm volatile("ldmatrix.sync.aligned.m8n8.x4.shared.b16 {%0,%1,%2,%3}, [%4];"
        : "=r"(r[0]), "=r"(r[1]), "=r"(r[2]), "=r"(r[3]) : "r"(addr));
}
__device__ __forceinline__ void mma_f16(float* c, const uint32_t* a, const uint32_t* b) {
    asm volatile(
        "mma.sync.aligned.m16n8k16.row.col.f32.f16.f16.f32 "
        "{%0,%1,%2,%3}, {%4,%5,%6,%7}, {%8,%9}, {%0,%1,%2,%3};"
        : "+f"(c[0]), "+f"(c[1]), "+f"(c[2]), "+f"(c[3])
        : "r"(a[0]), "r"(a[1]), "r"(a[2]), "r"(a[3]), "r"(b[0]), "r"(b[1]));
}
__device__ __forceinline__ float gelu_exact(float v) {
    return 0.5f * v * (1.0f + erff(v * 0.70710678118654752f));
}
__device__ __forceinline__ uint32_t pack_half2(float a, float b) {
    __half2 h = __floats2half2_rn(a, b);
    return *(uint32_t*)&h;
}

// ---------------- fp16 mma.sync GEMM: C[2048, N] = A[M,K] * B[N,K]^T ----------------
// 128x128x32 tiles, 5-stage cp.async, ldmatrix, fp32 accum, 2 CTAs/SM.
#define BM 128
#define BNT 128
#define BKT 32
#define PADW 20                  // words per row: 16 data + 4 pad (conflict-free ldsm)
#define NSTG 5
#define STW ((BM + BNT) * PADW)  // words per stage

template<bool OUT_HALF, bool HAS_BIAS, bool DO_GELU, bool DO_RES>
__global__ __launch_bounds__(256, 2) void mma_gemm(
    const __half* __restrict__ A, const __half* __restrict__ B,
    const float* __restrict__ bias, const float* __restrict__ res,
    void* __restrict__ Cout, int N_total, int K_total)
{
    extern __shared__ __align__(16) uint32_t smw[];

    const int tid = threadIdx.x;
    const int bm = blockIdx.x * BM;
    const int bn = blockIdx.y * BNT;
    const int wid = tid >> 5, lane = tid & 31;
    const int wm = (wid & 3) * 32;            // 4x2 warp grid: 32x64 per warp
    const int wn = (wid >> 2) * 64;
    const int grp = lane >> 2, tig = lane & 3;

    const uint32_t a_base = ((uint32_t)(wm + (lane & 15)) * PADW + ((lane >> 4) & 1) * 4) * 4;
    const uint32_t b_base = ((uint32_t)(wn + ((lane >> 4) & 1) * 8 + (lane & 7)) * PADW + ((lane >> 3) & 1) * 4) * 4;

    float acc[2][8][4];
#pragma unroll
    for (int i = 0; i < 2; ++i)
#pragma unroll
        for (int j = 0; j < 8; ++j)
#pragma unroll
            for (int q = 0; q < 4; ++q) acc[i][j][q] = 0.f;

    const int nIter = K_total / BKT;

    auto fill = [&](int st, int k0) {
        uint32_t* Ast = smw + st * STW;
        uint32_t* Bst = Ast + BM * PADW;
#pragma unroll
        for (int i = 0; i < 2; ++i) {
            int id = tid + i * 256;
            int row = id >> 2, c = id & 3;
            cp16(smem_u32(Ast + row * PADW + c * 4), A + (size_t)(bm + row) * K_total + k0 + c * 8);
        }
#pragma unroll
        for (int i = 0; i < 2; ++i) {
            int id = tid + i * 256;
            int row = id >> 2, c = id & 3;
            cp16(smem_u32(Bst + row * PADW + c * 4), B + (size_t)(bn + row) * K_total + k0 + c * 8);
        }
    };

#pragma unroll
    for (int s = 0; s < NSTG - 1; ++s) {
        fill(s, s * BKT);
        cp_commit();
    }

    for (int c = 0; c < nIter; ++c) {
        cp_wait<NSTG - 2>();
        __syncthreads();

        int nk = c + NSTG - 1;
        if (nk < nIter) fill(nk % NSTG, nk * BKT);
        cp_commit();

        const uint32_t sa = smem_u32(smw + (c % NSTG) * STW) + a_base;
        const uint32_t sb = smem_u32(smw + (c % NSTG) * STW + BM * PADW) + b_base;
#pragma unroll
        for (int ks = 0; ks < 2; ++ks) {
            uint32_t af[2][4];
#pragma unroll
            for (int mt = 0; mt < 2; ++mt)
                ldsm_x4(af[mt], sa + (uint32_t)(mt * 16 * PADW * 4 + ks * 32));
            uint32_t bf[8][2];
#pragma unroll
            for (int p = 0; p < 4; ++p) {
                uint32_t r[4];
                ldsm_x4(r, sb + (uint32_t)(p * 16 * PADW * 4 + ks * 32));
                bf[2 * p][0] = r[0]; bf[2 * p][1] = r[1];
                bf[2 * p + 1][0] = r[2]; bf[2 * p + 1][1] = r[3];
            }
#pragma unroll
            for (int mt = 0; mt < 2; ++mt)
#pragma unroll
                for (int nt = 0; nt < 8; ++nt)
                    mma_f16(acc[mt][nt], af[mt], bf[nt]);
        }
    }

    // epilogue
#pragma unroll
    for (int mt = 0; mt < 2; ++mt) {
        const int r0 = bm + wm + mt * 16 + grp;
#pragma unroll
        for (int nt = 0; nt < 8; ++nt) {
            const int cn = bn + wn + nt * 8 + tig * 2;
#pragma unroll
            for (int hh = 0; hh < 2; ++hh) {
                const int row = r0 + hh * 8;
                float v0 = acc[mt][nt][hh * 2 + 0];
                float v1 = acc[mt][nt][hh * 2 + 1];
                if (HAS_BIAS) { v0 += __ldg(&bias[cn]); v1 += __ldg(&bias[cn + 1]); }
                if (DO_GELU) { v0 = gelu_exact(v0); v1 = gelu_exact(v1); }
                if (DO_RES) {
                    const float2 rv = *(const float2*)(res + (size_t)row * N_total + cn);
                    v0 += rv.x; v1 += rv.y;
                }
                if (OUT_HALF) {
                    uint32_t hv = pack_half2(v0, v1);
                    *(uint32_t*)((__half*)Cout + (size_t)row * N_total + cn) = hv;
                } else {
                    *(float2*)((float*)Cout + (size_t)row * N_total + cn) = make_float2(v0, v1);
                }
            }
        }
    }
}

// ---------------- fused prep: all weight transposes + emb f2h + bias concat ----------------
// linear grid decode:
//   [0, 24576)              : weight transposes (2 layers x 12288 tiles)
//       per layer: [0,4096) wq/wk/wv/wo (1024 tiles each), [4096,8192) w1, [8192,12288) w2
//   [24576, 56576)          : emb f2h (32000 tiles of 1024 elements)
//   [56576, 56600)          : bias concat (6144 elements)
#define TP_W  24576
#define TP_E  56576
#define TP_END 56600

__global__ __launch_bounds__(256) void prep_all(
    const float* __restrict__ wq, const float* __restrict__ wk,
    const float* __restrict__ wv, const float* __restrict__ wo,
    const float* __restrict__ w1, const float* __restrict__ w2,
    const float* __restrict__ emb,
    const float* __restrict__ bq, const float* __restrict__ bk,
    const float* __restrict__ bv)
{
    const int b = blockIdx.x;
    const int tid = threadIdx.x;

    if (b < TP_W) {
        __shared__ float t[32][33];
        const int l = b / 12288;
        const int r = b % 12288;
        const float* src;
        __half* dst;
        int R, C, tile;
        __half* base = g_wT + (size_t)l * 12 * MB_ELT;
        if (r < 4096) {
            int w = r >> 10;
            tile = r & 1023;
            R = D; C = D;
            src = (w == 0 ? wq : w == 1 ? wk : w == 2 ? wv : wo) + (size_t)l * D * D;
            dst = base + (size_t)w * MB_ELT;
        } else if (r < 8192) {
            tile = r - 4096;
            R = D; C = DF;
            src = w1 + (size_t)l * D * DF;
            dst = base + 4 * MB_ELT;
        } else {
            tile = r - 8192;
            R = DF; C = D;
            src = w2 + (size_t)l * DF * D;
            dst = base + 8 * MB_ELT;
        }
        const int tc = C >> 5;
        const int r0 = (tile / tc) * 32;
        const int c0 = (tile % tc) * 32;
        const int x = tid & 31, y = tid >> 5;
#pragma unroll
        for (int i = y; i < 32; i += 8) t[i][x] = src[(size_t)(r0 + i) * C + c0 + x];
        __syncthreads();
#pragma unroll
        for (int i = y; i < 32; i += 8)
            dst[(size_t)(c0 + i) * R + r0 + x] = __float2half_rn(t[x][i]);
    } else if (b < TP_E) {
        size_t i0 = (size_t)(b - TP_W) * 1024 + tid * 4;
        float4 v = *(const float4*)(emb + i0);
        uint32_t h0 = pack_half2(v.x, v.y);
        uint32_t h1 = pack_half2(v.z, v.w);
        *(uint2*)(g_embT + i0) = make_uint2(h0, h1);
    } else {
        int idx = (b - TP_E) * 256 + tid;
        if (idx < NL * 3 * D) {
            int l = idx / (3 * D);
            int i = idx % (3 * D);
            float v = (i < D) ? bq[l * D + i] : (i < 2 * D) ? bk[l * D + i - D] : bv[l * D + i - 2 * D];
            g_bqkv[idx] = v;
        }
    }
}

// ---------------- small kernels ----------------
__global__ void embed_kernel(const int* __restrict__ ids,
                             const float* __restrict__ emb,
                             const float* __restrict__ pos) {
    int idx = blockIdx.x * blockDim.x + threadIdx.x;
    if (idx >= S * D) return;
    int s = idx >> 10;
    int d = idx & (D - 1);
    g_x[idx] = emb[(size_t)ids[s] * D + d] + pos[idx];
}

__global__ __launch_bounds__(256) void ln_kernel(const float* __restrict__ x,
                                                 __half* __restrict__ out,
                                                 const float* __restrict__ g,
                                                 const float* __restrict__ b) {
    __shared__ float rs[256], rs2[256];
    int row = blockIdx.x;
    int t = threadIdx.x;
    const float* xr = x + (size_t)row * D;
    float s = 0.f, s2 = 0.f;
#pragma unroll
    for (int i = t; i < D; i += 256) { float v = xr[i]; s += v; s2 += v * v; }
    rs[t] = s; rs2[t] = s2;
    __syncthreads();
    for (int off = 128; off > 0; off >>= 1) {
        if (t < off) { rs[t] += rs[t + off]; rs2[t] += rs2[t + off]; }
        __syncthreads();
    }
    float mu = rs[0] * (1.0f / D);
    float var = rs2[0] * (1.0f / D) - mu * mu;
    float inv = rsqrtf(var + LN_EPS);
    __half* orow = out + (size_t)row * D;
#pragma unroll
    for (int i = t; i < D; i += 256)
        orow[i] = __float2half_rn((xr[i] - mu) * inv * g[i] + b[i]);
}

// ---------------- tiled local attention ----------------
#define TQ 64
#define JW 320
#define SCP 324

__global__ __launch_bounds__(256) void attn_tiled() {
    extern __shared__ __align__(16) float asm_[];
    float* Qs = asm_;                 // [64][64]
    float* KV = asm_ + 4096;          // [64][64]
    float* sc = asm_ + 8192;          // [64][SCP]
    float* invl = sc + 64 * SCP;      // [64]

    const int q0 = blockIdx.x * TQ;
    const int head = blockIdx.y;
    const int tid = threadIdx.x;
    const int RS = 3 * D;
    const int qoff = head * HD, koff = D + head * HD, voff = 2 * D + head * HD;
    const int jbase = q0 - HALFW;

    for (int i = tid; i < TQ * 16; i += 256) {
        int row = i >> 4, c4 = (i & 15) * 4;
        uint2 u = *(const uint2*)&g_qkv[(size_t)(q0 + row) * RS + qoff + c4];
        float2 f0 = __half22float2(*(__half2*)&u.x);
        float2 f1 = __half22float2(*(__half2*)&u.y);
        float* dst = &Qs[row * 64 + c4];
        dst[0] = f0.x; dst[1] = f0.y; dst[2] = f1.x; dst[3] = f1.y;
    }

    const int ttq = (tid >> 4) << 2;
    const int ttj = (tid & 15) << 2;

    // ---- scores ----
#pragma unroll 1
    for (int jt = 0; jt < 5; ++jt) {
        __syncthreads();
        for (int i = tid; i < TQ * 16; i += 256) {
            int row = i >> 4, c4 = (i & 15) * 4;
            int j = jbase + jt * 64 + row;
            j = min(max(j, 0), S - 1);
            uint2 u = *(const uint2*)&g_qkv[(size_t)j * RS + koff + c4];
            float2 f0 = __half22float2(*(__half2*)&u.x);
            float2 f1 = __half22float2(*(__half2*)&u.y);
            float* dst = &KV[row * 64 + c4];
            dst[0] = f0.x; dst[1] = f0.y; dst[2] = f1.x; dst[3] = f1.y;
        }
        __syncthreads();
        float a[4][4];
#pragma unroll
        for (int i = 0; i < 4; ++i)
#pragma unroll
            for (int j = 0; j < 4; ++j) a[i][j] = 0.f;
#pragma unroll
        for (int d = 0; d < 64; d += 4) {
            float4 qv[4], kv[4];
#pragma unroll
            for (int i = 0; i < 4; ++i) {
                qv[i] = *(const float4*)&Qs[(ttq + i) * 64 + d];
                kv[i] = *(const float4*)&KV[(ttj + i) * 64 + d];
            }
#pragma unroll
            for (int i = 0; i < 4; ++i)
#pragma unroll
                for (int j = 0; j < 4; ++j)
                    a[i][j] += qv[i].x * kv[j].x + qv[i].y * kv[j].y +
                               qv[i].z * kv[j].z + qv[i].w * kv[j].w;
        }
#pragma unroll
        for (int i = 0; i < 4; ++i)
#pragma unroll
            for (int j = 0; j < 4; ++j) {
                int qq = ttq + i;
                int jj = jt * 64 + ttj + j;
                int jg = jbase + jj;
                int qg = q0 + qq;
                bool ok = (jg >= 0) && (jg < S) && (abs(qg - jg) <= HALFW);
                sc[qq * SCP + jj] = ok ? a[i][j] * ATT_SCALE : -1e30f;
            }
    }
    __syncthreads();

    // ---- softmax ----
    const int wid = tid >> 5, lane = tid & 31;
    for (int r = 0; r < 8; ++r) {
        int q = wid * 8 + r;
        float m = -1e30f;
        for (int j = lane; j < JW; j += 32) m = fmaxf(m, sc[q * SCP + j]);
#pragma unroll
        for (int off = 16; off > 0; off >>= 1) m = fmaxf(m, __shfl_xor_sync(0xffffffffu, m, off));
        float s = 0.f;
        for (int j = lane; j < JW; j += 32) {
            float e = __expf(sc[q * SCP + j] - m);
            sc[q * SCP + j] = e;
            s += e;
        }
#pragma unroll
        for (int off = 16; off > 0; off >>= 1) s += __shfl_xor_sync(0xffffffffu, s, off);
        if (lane == 0) invl[q] = 1.0f / s;
    }
    __syncthreads();

    // ---- AV ----
    float o[4][4];
#pragma unroll
    for (int i = 0; i < 4; ++i)
#pragma unroll
        for (int j = 0; j < 4; ++j) o[i][j] = 0.f;
#pragma unroll 1
    for (int jt = 0; jt < 5; ++jt) {
        __syncthreads();
        for (int i = tid; i < TQ * 16; i += 256) {
            int row = i >> 4, c4 = (i & 15) * 4;
            int j = jbase + jt * 64 + row;
            j = min(max(j, 0), S - 1);
            uint2 u = *(const uint2*)&g_qkv[(size_t)j * RS + voff + c4];
            float2 f0 = __half22float2(*(__half2*)&u.x);
            float2 f1 = __half22float2(*(__half2*)&u.y);
            float* dst = &KV[row * 64 + c4];
            dst[0] = f0.x; dst[1] = f0.y; dst[2] = f1.x; dst[3] = f1.y;
        }
        __syncthreads();
#pragma unroll 4
        for (int jj = 0; jj < 64; ++jj) {
            float4 vv = *(const float4*)&KV[jj * 64 + ttj];
            float p[4];
#pragma unroll
            for (int i = 0; i < 4; ++i) p[i] = sc[(ttq + i) * SCP + jt * 64 + jj];
#pragma unroll
            for (int i = 0; i < 4; ++i) {
                o[i][0] += p[i] * vv.x;
                o[i][1] += p[i] * vv.y;
                o[i][2] += p[i] * vv.z;
                o[i][3] += p[i] * vv.w;
            }
        }
    }
#pragma unroll
    for (int i = 0; i < 4; ++i) {
        int q = ttq + i;
        float il = invl[q];
        uint32_t h0 = pack_half2(o[i][0] * il, o[i][1] * il);
        uint32_t h1 = pack_half2(o[i][2] * il, o[i][3] * il);
        *(uint2*)&g_att[(size_t)(q0 + q) * D + qoff + ttj] = make_uint2(h0, h1);
    }
}

// ---------------- host ----------------
extern "C" void kernel_launch(void* const* d_in, const int* in_sizes, int n_in,
                              void* d_out, int out_size) {
    const int*   ids   = (const int*)  d_in[0];
    const float* emb   = (const float*)d_in[1];
    const float* pos   = (const float*)d_in[2];
    const float* wq    = (const float*)d_in[3];
    const float* bq    = (const float*)d_in[4];
    const float* wk    = (const float*)d_in[5];
    const float* bk    = (const float*)d_in[6];
    const float* wv    = (const float*)d_in[7];
    const float* bv    = (const float*)d_in[8];
    const float* wo    = (const float*)d_in[9];
    const float* bo    = (const float*)d_in[10];
    const float* w1    = (const float*)d_in[11];
    const float* b1    = (const float*)d_in[12];
    const float* w2    = (const float*)d_in[13];
    const float* b2    = (const float*)d_in[14];
    const float* ln1_g = (const float*)d_in[15];
    const float* ln1_b = (const float*)d_in[16];
    const float* ln2_g = (const float*)d_in[17];
    const float* ln2_b = (const float*)d_in[18];
    const float* out_g = (const float*)d_in[19];
    const float* out_b = (const float*)d_in[20];
    float* logits = (float*)d_out;

    float *x, *bqkv;
    __half *h, *qkv, *att, *ffn, *wT, *embT;
    cudaGetSymbolAddress((void**)&x,    g_x);
    cudaGetSymbolAddress((void**)&h,    g_h);
    cudaGetSymbolAddress((void**)&qkv,  g_qkv);
    cudaGetSymbolAddress((void**)&att,  g_att);
    cudaGetSymbolAddress((void**)&ffn,  g_ffn);
    cudaGetSymbolAddress((void**)&wT,   g_wT);
    cudaGetSymbolAddress((void**)&embT, g_embT);
    cudaGetSymbolAddress((void**)&bqkv, g_bqkv);

    const int GEMM_SM = STW * 4 * NSTG;                        // 102400 B
    const int ATTN_SM = (4096 + 4096 + 64 * SCP + 64) * 4;     // ~116 KB
    cudaFuncSetAttribute(mma_gemm<true,  true,  false, false>, cudaFuncAttributeMaxDynamicSharedMemorySize, GEMM_SM);
    cudaFuncSetAttribute(mma_gemm<false, true,  false, true >, cudaFuncAttributeMaxDynamicSharedMemorySize, GEMM_SM);
    cudaFuncSetAttribute(mma_gemm<true,  true,  true,  false>, cudaFuncAttributeMaxDynamicSharedMemorySize, GEMM_SM);
    cudaFuncSetAttribute(mma_gemm<false, false, false, false>, cudaFuncAttributeMaxDynamicSharedMemorySize, GEMM_SM);
    cudaFuncSetAttribute(attn_tiled, cudaFuncAttributeMaxDynamicSharedMemorySize, ATTN_SM);

    // ---- launch 0: fused prep (transposes + emb f2h + bias concat) ----
    prep_all<<<TP_END, 256>>>(wq, wk, wv, wo, w1, w2, emb, bq, bk, bv);

    // ---- launch 1: embedding ----
    embed_kernel<<<(S * D + 255) / 256, 256>>>(ids, emb, pos);

    for (int l = 0; l < NL; ++l) {
        __half* base = wT + (size_t)l * 12 * MB_ELT;

        ln_kernel<<<S, 256>>>(x, h, ln1_g + l * D, ln1_b + l * D);

        // qkv = h @ Wqkv^T + b   (N = 3072), half out
        mma_gemm<true, true, false, false><<<dim3(S / BM, 3 * D / BNT), 256, GEMM_SM>>>(
            h, base + 0 * MB_ELT, bqkv + (size_t)l * 3 * D, nullptr, qkv, 3 * D, D);

        attn_tiled<<<dim3(S / TQ, H), 256, ATTN_SM>>>();

        // x = x + att @ wo^T + bo (fp32 out)    <-- launch index 5 on layer 0: ncu target
        mma_gemm<false, true, false, true><<<dim3(S / BM, D / BNT), 256, GEMM_SM>>>(
            att, base + 3 * MB_ELT, bo + (size_t)l * D, x, x, D, D);

        ln_kernel<<<S, 256>>>(x, h, ln2_g + l * D, ln2_b + l * D);

        // ffn = gelu(h @ w1^T + b1), half out
        mma_gemm<true, true, true, false><<<dim3(S / BM, DF / BNT), 256, GEMM_SM>>>(
            h, base + 4 * MB_ELT, b1 + (size_t)l * DF, nullptr, ffn, DF, D);

        // x = x + ffn @ w2^T + b2 (fp32 out)
        mma_gemm<false, true, false, true><<<dim3(S / BM, D / BNT), 256, GEMM_SM>>>(
            ffn, base + 8 * MB_ELT, b2 + (size_t)l * D, x, x, D, DF);
    }

    ln_kernel<<<S, 256>>>(x, h, out_g, out_b);

    // logits = h @ emb^T (fp32 out)
    mma_gemm<false, false, false, false><<<dim3(S / BM, VOCAB / BNT), 256, GEMM_SM>>>(
        h, embT, nullptr, nullptr, logits, VOCAB, D);
}

// round 9
// speedup vs baseline: 6.6764x; 1.0312x over previous
#include <cuda_runtime.h>
#include <cuda_fp16.h>
#include <math.h>
#include <stdint.h>

// ---------------- problem constants ----------------
#define S 2048
#define D 1024
#define H 16
#define HD 64
#define DF 4096
#define NL 2
#define VOCAB 32000
#define HALFW 128
#define ATT_SCALE 0.125f
#define LN_EPS 1e-5f
#define MB_ELT (1024*1024)

// ---------------- scratch (device globals) ----------------
__device__ float  g_x[S * D];               // residual stream (fp32)
__device__ __half g_h[S * D];               // LN output (GEMM A)
__device__ __half g_qkv[S * 3 * D];
__device__ __half g_att[S * D];
__device__ __half g_ffn[S * DF];
__device__ __half g_wT[NL * 12 * MB_ELT];   // per layer: qkvT(3M) woT(1M) w1T(4M) w2T(4M)
__device__ __half g_embT[VOCAB * D];
__device__ float  g_bqkv[NL * 3 * D];

// ---------------- helpers ----------------
__device__ __forceinline__ uint32_t smem_u32(const void* p) {
    uint32_t a;
    asm("{ .reg .u64 t; cvta.to.shared.u64 t, %1; cvt.u32.u64 %0, t; }" : "=r"(a) : "l"(p));
    return a;
}
__device__ __forceinline__ void cp16(uint32_t dst, const void* src) {
    asm volatile("cp.async.cg.shared.global [%0], [%1], 16;" :: "r"(dst), "l"(src));
}
__device__ __forceinline__ void cp_commit() {
    asm volatile("cp.async.commit_group;" ::: "memory");
}
template<int N>
__device__ __forceinline__ void cp_wait() {
    asm volatile("cp.async.wait_group %0;" :: "n"(N) : "memory");
}
__device__ __forceinline__ void ldsm_x4(uint32_t* r, uint32_t addr) {
    asm volatile("ldmatrix.sync.aligned.m8n8.x4.shared.b16 {%0,%1,%2,%3}, [%4];"
        : "=r"(r[0]), "=r"(r[1]), "=r"(r[2]), "=r"(r[3]) : "r"(addr));
}
__device__ __forceinline__ void mma_f16(float* c, const uint32_t* a, const uint32_t* b) {
    asm volatile(
        "mma.sync.aligned.m16n8k16.row.col.f32.f16.f16.f32 "
        "{%0,%1,%2,%3}, {%4,%5,%6,%7}, {%8,%9}, {%0,%1,%2,%3};"
        : "+f"(c[0]), "+f"(c[1]), "+f"(c[2]), "+f"(c[3])
        : "r"(a[0]), "r"(a[1]), "r"(a[2]), "r"(a[3]), "r"(b[0]), "r"(b[1]));
}
__device__ __forceinline__ float gelu_exact(float v) {
    return 0.5f * v * (1.0f + erff(v * 0.70710678118654752f));
}
__device__ __forceinline__ uint32_t pack_half2(float a, float b) {
    __half2 h = __floats2half2_rn(a, b);
    return *(uint32_t*)&h;
}

// ---------------- fp16 mma.sync GEMM: C[2048, N] = A[M,K] * B[N,K]^T ----------------
// BM=128, BNT in {64,128}, BKT=64, 3-stage cp.async, ldmatrix, fp32 accum, 2 CTAs/SM.
#define BM 128
#define BKT 64
#define PADW 36                  // words per row: 32 data + 4 pad (conflict-free ldsm)
#define NSTG 3

template<int BNT, bool OUT_HALF, bool HAS_BIAS, bool DO_GELU, bool DO_RES>
__global__ __launch_bounds__(256, 2) void mma_gemm(
    const __half* __restrict__ A, const __half* __restrict__ B,
    const float* __restrict__ bias, const float* __restrict__ res,
    void* __restrict__ Cout, int N_total, int K_total)
{
    constexpr int NT = (BNT == 128) ? 8 : 4;      // 8-col B tiles per warp
    constexpr int NP = NT / 2;                    // ldsm.x4 B loads per ks
    constexpr int WNW = (BNT == 128) ? 64 : 32;   // warp tile width
    constexpr int STW = (BM + BNT) * PADW;        // words per stage

    extern __shared__ __align__(16) uint32_t smw[];

    const int tid = threadIdx.x;
    const int bm = blockIdx.x * BM;
    const int bn = blockIdx.y * BNT;
    const int wid = tid >> 5, lane = tid & 31;
    const int wm = (wid & 3) * 32;                // 4x2 warp grid: 32 x WNW per warp
    const int wn = (wid >> 2) * WNW;
    const int grp = lane >> 2, tig = lane & 3;

    const uint32_t a_base = ((uint32_t)(wm + (lane & 15)) * PADW + ((lane >> 4) & 1) * 4) * 4;
    const uint32_t b_base = ((uint32_t)(wn + ((lane >> 4) & 1) * 8 + (lane & 7)) * PADW + ((lane >> 3) & 1) * 4) * 4;

    float acc[2][NT][4];
#pragma unroll
    for (int i = 0; i < 2; ++i)
#pragma unroll
        for (int j = 0; j < NT; ++j)
#pragma unroll
            for (int q = 0; q < 4; ++q) acc[i][j][q] = 0.f;

    const int nIter = K_total / BKT;

    // fill one stage: rows have 8 chunks of 16B (64 halfs)
    auto fill = [&](int st, int k0) {
        uint32_t* Ast = smw + st * STW;
        uint32_t* Bst = Ast + BM * PADW;
#pragma unroll
        for (int i = 0; i < 4; ++i) {             // A: 128 rows x 8 chunks = 1024
            int id = tid + i * 256;
            int row = id >> 3, c = id & 7;
            cp16(smem_u32(Ast + row * PADW + c * 4), A + (size_t)(bm + row) * K_total + k0 + c * 8);
        }
#pragma unroll
        for (int i = 0; i < BNT / 32; ++i) {      // B: BNT rows x 8 chunks
            int id = tid + i * 256;
            int row = id >> 3, c = id & 7;
            cp16(smem_u32(Bst + row * PADW + c * 4), B + (size_t)(bn + row) * K_total + k0 + c * 8);
        }
    };

#pragma unroll
    for (int s = 0; s < NSTG - 1; ++s) {
        fill(s, s * BKT);
        cp_commit();
    }

    for (int c = 0; c < nIter; ++c) {
        cp_wait<NSTG - 2>();
        __syncthreads();

        int nk = c + NSTG - 1;
        if (nk < nIter) fill(nk % NSTG, nk * BKT);
        cp_commit();

        const uint32_t sa = smem_u32(smw + (c % NSTG) * STW) + a_base;
        const uint32_t sb = smem_u32(smw + (c % NSTG) * STW + BM * PADW) + b_base;
#pragma unroll
        for (int ks = 0; ks < 4; ++ks) {
            uint32_t af[2][4];
#pragma unroll
            for (int mt = 0; mt < 2; ++mt)
                ldsm_x4(af[mt], sa + (uint32_t)(mt * 16 * PADW * 4 + ks * 32));
            uint32_t bf[NT][2];
#pragma unroll
            for (int p = 0; p < NP; ++p) {
                uint32_t r[4];
                ldsm_x4(r, sb + (uint32_t)(p * 16 * PADW * 4 + ks * 32));
                bf[2 * p][0] = r[0]; bf[2 * p][1] = r[1];
                bf[2 * p + 1][0] = r[2]; bf[2 * p + 1][1] = r[3];
            }
#pragma unroll
            for (int mt = 0; mt < 2; ++mt)
#pragma unroll
                for (int nt = 0; nt < NT; ++nt)
                    mma_f16(acc[mt][nt], af[mt], bf[nt]);
        }
    }

    // epilogue
#pragma unroll
    for (int mt = 0; mt < 2; ++mt) {
        const int r0 = bm + wm + mt * 16 + grp;
#pragma unroll
        for (int nt = 0; nt < NT; ++nt) {
            const int cn = bn + wn + nt * 8 + tig * 2;
#pragma unroll
            for (int hh = 0; hh < 2; ++hh) {
                const int row = r0 + hh * 8;
                float v0 = acc[mt][nt][hh * 2 + 0];
                float v1 = acc[mt][nt][hh * 2 + 1];
                if (HAS_BIAS) { v0 += __ldg(&bias[cn]); v1 += __ldg(&bias[cn + 1]); }
                if (DO_GELU) { v0 = gelu_exact(v0); v1 = gelu_exact(v1); }
                if (DO_RES) {
                    const float2 rv = *(const float2*)(res + (size_t)row * N_total + cn);
                    v0 += rv.x; v1 += rv.y;
                }
                if (OUT_HALF) {
                    uint32_t hv = pack_half2(v0, v1);
                    *(uint32_t*)((__half*)Cout + (size_t)row * N_total + cn) = hv;
                } else {
                    *(float2*)((float*)Cout + (size_t)row * N_total + cn) = make_float2(v0, v1);
                }
            }
        }
    }
}

// ---------------- fused prep: all weight transposes + emb f2h + bias concat ----------------
#define TP_W  24576
#define TP_E  56576
#define TP_END 56600

__global__ __launch_bounds__(256) void prep_all(
    const float* __restrict__ wq, const float* __restrict__ wk,
    const float* __restrict__ wv, const float* __restrict__ wo,
    const float* __restrict__ w1, const float* __restrict__ w2,
    const float* __restrict__ emb,
    const float* __restrict__ bq, const float* __restrict__ bk,
    const float* __restrict__ bv)
{
    const int b = blockIdx.x;
    const int tid = threadIdx.x;

    if (b < TP_W) {
        __shared__ float t[32][33];
        const int l = b / 12288;
        const int r = b % 12288;
        const float* src;
        __half* dst;
        int R, C, tile;
        __half* base = g_wT + (size_t)l * 12 * MB_ELT;
        if (r < 4096) {
            int w = r >> 10;
            tile = r & 1023;
            R = D; C = D;
            src = (w == 0 ? wq : w == 1 ? wk : w == 2 ? wv : wo) + (size_t)l * D * D;
            dst = base + (size_t)w * MB_ELT;
        } else if (r < 8192) {
            tile = r - 4096;
            R = D; C = DF;
            src = w1 + (size_t)l * D * DF;
            dst = base + 4 * MB_ELT;
        } else {
            tile = r - 8192;
            R = DF; C = D;
            src = w2 + (size_t)l * DF * D;
            dst = base + 8 * MB_ELT;
        }
        const int tc = C >> 5;
        const int r0 = (tile / tc) * 32;
        const int c0 = (tile % tc) * 32;
        const int x = tid & 31, y = tid >> 5;
#pragma unroll
        for (int i = y; i < 32; i += 8) t[i][x] = src[(size_t)(r0 + i) * C + c0 + x];
        __syncthreads();
#pragma unroll
        for (int i = y; i < 32; i += 8)
            dst[(size_t)(c0 + i) * R + r0 + x] = __float2half_rn(t[x][i]);
    } else if (b < TP_E) {
        size_t i0 = (size_t)(b - TP_W) * 1024 + tid * 4;
        float4 v = *(const float4*)(emb + i0);
        uint32_t h0 = pack_half2(v.x, v.y);
        uint32_t h1 = pack_half2(v.z, v.w);
        *(uint2*)(g_embT + i0) = make_uint2(h0, h1);
    } else {
        int idx = (b - TP_E) * 256 + tid;
        if (idx < NL * 3 * D) {
            int l = idx / (3 * D);
            int i = idx % (3 * D);
            float v = (i < D) ? bq[l * D + i] : (i < 2 * D) ? bk[l * D + i - D] : bv[l * D + i - 2 * D];
            g_bqkv[idx] = v;
        }
    }
}

// ---------------- small kernels ----------------
__global__ void embed_kernel(const int* __restrict__ ids,
                             const float* __restrict__ emb,
                             const float* __restrict__ pos) {
    int idx = blockIdx.x * blockDim.x + threadIdx.x;
    if (idx >= S * D) return;
    int s = idx >> 10;
    int d = idx & (D - 1);
    g_x[idx] = emb[(size_t)ids[s] * D + d] + pos[idx];
}

__global__ __launch_bounds__(256) void ln_kernel(const float* __restrict__ x,
                                                 __half* __restrict__ out,
                                                 const float* __restrict__ g,
                                                 const float* __restrict__ b) {
    __shared__ float rs[256], rs2[256];
    int row = blockIdx.x;
    int t = threadIdx.x;
    const float* xr = x + (size_t)row * D;
    float s = 0.f, s2 = 0.f;
#pragma unroll
    for (int i = t; i < D; i += 256) { float v = xr[i]; s += v; s2 += v * v; }
    rs[t] = s; rs2[t] = s2;
    __syncthreads();
    for (int off = 128; off > 0; off >>= 1) {
        if (t < off) { rs[t] += rs[t + off]; rs2[t] += rs2[t + off]; }
        __syncthreads();
    }
    float mu = rs[0] * (1.0f / D);
    float var = rs2[0] * (1.0f / D) - mu * mu;
    float inv = rsqrtf(var + LN_EPS);
    __half* orow = out + (size_t)row * D;
#pragma unroll
    for (int i = t; i < D; i += 256)
        orow[i] = __float2half_rn((xr[i] - mu) * inv * g[i] + b[i]);
}

// ---------------- tiled local attention ----------------
#define TQ 64
#define JW 320
#define SCP 324

__global__ __launch_bounds__(256) void attn_tiled() {
    extern __shared__ __align__(16) float asm_[];
    float* Qs = asm_;                 // [64][64]
    float* KV = asm_ + 4096;          // [64][64]
    float* sc = asm_ + 8192;          // [64][SCP]
    float* invl = sc + 64 * SCP;      // [64]

    const int q0 = blockIdx.x * TQ;
    const int head = blockIdx.y;
    const int tid = threadIdx.x;
    const int RS = 3 * D;
    const int qoff = head * HD, koff = D + head * HD, voff = 2 * D + head * HD;
    const int jbase = q0 - HALFW;

    for (int i = tid; i < TQ * 16; i += 256) {
        int row = i >> 4, c4 = (i & 15) * 4;
        uint2 u = *(const uint2*)&g_qkv[(size_t)(q0 + row) * RS + qoff + c4];
        float2 f0 = __half22float2(*(__half2*)&u.x);
        float2 f1 = __half22float2(*(__half2*)&u.y);
        float* dst = &Qs[row * 64 + c4];
        dst[0] = f0.x; dst[1] = f0.y; dst[2] = f1.x; dst[3] = f1.y;
    }

    const int ttq = (tid >> 4) << 2;
    const int ttj = (tid & 15) << 2;

    // ---- scores ----
#pragma unroll 1
    for (int jt = 0; jt < 5; ++jt) {
        __syncthreads();
        for (int i = tid; i < TQ * 16; i += 256) {
            int row = i >> 4, c4 = (i & 15) * 4;
            int j = jbase + jt * 64 + row;
            j = min(max(j, 0), S - 1);
            uint2 u = *(const uint2*)&g_qkv[(size_t)j * RS + koff + c4];
            float2 f0 = __half22float2(*(__half2*)&u.x);
            float2 f1 = __half22float2(*(__half2*)&u.y);
            float* dst = &KV[row * 64 + c4];
            dst[0] = f0.x; dst[1] = f0.y; dst[2] = f1.x; dst[3] = f1.y;
        }
        __syncthreads();
        float a[4][4];
#pragma unroll
        for (int i = 0; i < 4; ++i)
#pragma unroll
            for (int j = 0; j < 4; ++j) a[i][j] = 0.f;
#pragma unroll
        for (int d = 0; d < 64; d += 4) {
            float4 qv[4], kv[4];
#pragma unroll
            for (int i = 0; i < 4; ++i) {
                qv[i] = *(const float4*)&Qs[(ttq + i) * 64 + d];
                kv[i] = *(const float4*)&KV[(ttj + i) * 64 + d];
            }
#pragma unroll
            for (int i = 0; i < 4; ++i)
#pragma unroll
                for (int j = 0; j < 4; ++j)
                    a[i][j] += qv[i].x * kv[j].x + qv[i].y * kv[j].y +
                               qv[i].z * kv[j].z + qv[i].w * kv[j].w;
        }
#pragma unroll
        for (int i = 0; i < 4; ++i)
#pragma unroll
            for (int j = 0; j < 4; ++j) {
                int qq = ttq + i;
                int jj = jt * 64 + ttj + j;
                int jg = jbase + jj;
                int qg = q0 + qq;
                bool ok = (jg >= 0) && (jg < S) && (abs(qg - jg) <= HALFW);
                sc[qq * SCP + jj] = ok ? a[i][j] * ATT_SCALE : -1e30f;
            }
    }
    __syncthreads();

    // ---- softmax ----
    const int wid = tid >> 5, lane = tid & 31;
    for (int r = 0; r < 8; ++r) {
        int q = wid * 8 + r;
        float m = -1e30f;
        for (int j = lane; j < JW; j += 32) m = fmaxf(m, sc[q * SCP + j]);
#pragma unroll
        for (int off = 16; off > 0; off >>= 1) m = fmaxf(m, __shfl_xor_sync(0xffffffffu, m, off));
        float s = 0.f;
        for (int j = lane; j < JW; j += 32) {
            float e = __expf(sc[q * SCP + j] - m);
            sc[q * SCP + j] = e;
            s += e;
        }
#pragma unroll
        for (int off = 16; off > 0; off >>= 1) s += __shfl_xor_sync(0xffffffffu, s, off);
        if (lane == 0) invl[q] = 1.0f / s;
    }
    __syncthreads();

    // ---- AV ----
    float o[4][4];
#pragma unroll
    for (int i = 0; i < 4; ++i)
#pragma unroll
        for (int j = 0; j < 4; ++j) o[i][j] = 0.f;
#pragma unroll 1
    for (int jt = 0; jt < 5; ++jt) {
        __syncthreads();
        for (int i = tid; i < TQ * 16; i += 256) {
            int row = i >> 4, c4 = (i & 15) * 4;
            int j = jbase + jt * 64 + row;
            j = min(max(j, 0), S - 1);
            uint2 u = *(const uint2*)&g_qkv[(size_t)j * RS + voff + c4];
            float2 f0 = __half22float2(*(__half2*)&u.x);
            float2 f1 = __half22float2(*(__half2*)&u.y);
            float* dst = &KV[row * 64 + c4];
            dst[0] = f0.x; dst[1] = f0.y; dst[2] = f1.x; dst[3] = f1.y;
        }
        __syncthreads();
#pragma unroll 4
        for (int jj = 0; jj < 64; ++jj) {
            float4 vv = *(const float4*)&KV[jj * 64 + ttj];
            float p[4];
#pragma unroll
            for (int i = 0; i < 4; ++i) p[i] = sc[(ttq + i) * SCP + jt * 64 + jj];
#pragma unroll
            for (int i = 0; i < 4; ++i) {
                o[i][0] += p[i] * vv.x;
                o[i][1] += p[i] * vv.y;
                o[i][2] += p[i] * vv.z;
                o[i][3] += p[i] * vv.w;
            }
        }
    }
#pragma unroll
    for (int i = 0; i < 4; ++i) {
        int q = ttq + i;
        float il = invl[q];
        uint32_t h0 = pack_half2(o[i][0] * il, o[i][1] * il);
        uint32_t h1 = pack_half2(o[i][2] * il, o[i][3] * il);
        *(uint2*)&g_att[(size_t)(q0 + q) * D + qoff + ttj] = make_uint2(h0, h1);
    }
}

// ---------------- host ----------------
extern "C" void kernel_launch(void* const* d_in, const int* in_sizes, int n_in,
                              void* d_out, int out_size) {
    const int*   ids   = (const int*)  d_in[0];
    const float* emb   = (const float*)d_in[1];
    const float* pos   = (const float*)d_in[2];
    const float* wq    = (const float*)d_in[3];
    const float* bq    = (const float*)d_in[4];
    const float* wk    = (const float*)d_in[5];
    const float* bk    = (const float*)d_in[6];
    const float* wv    = (const float*)d_in[7];
    const float* bv    = (const float*)d_in[8];
    const float* wo    = (const float*)d_in[9];
    const float* bo    = (const float*)d_in[10];
    const float* w1    = (const float*)d_in[11];
    const float* b1    = (const float*)d_in[12];
    const float* w2    = (const float*)d_in[13];
    const float* b2    = (const float*)d_in[14];
    const float* ln1_g = (const float*)d_in[15];
    const float* ln1_b = (const float*)d_in[16];
    const float* ln2_g = (const float*)d_in[17];
    const float* ln2_b = (const float*)d_in[18];
    const float* out_g = (const float*)d_in[19];
    const float* out_b = (const float*)d_in[20];
    float* logits = (float*)d_out;

    float *x, *bqkv;
    __half *h, *qkv, *att, *ffn, *wT, *embT;
    cudaGetSymbolAddress((void**)&x,    g_x);
    cudaGetSymbolAddress((void**)&h,    g_h);
    cudaGetSymbolAddress((void**)&qkv,  g_qkv);
    cudaGetSymbolAddress((void**)&att,  g_att);
    cudaGetSymbolAddress((void**)&ffn,  g_ffn);
    cudaGetSymbolAddress((void**)&wT,   g_wT);
    cudaGetSymbolAddress((void**)&embT, g_embT);
    cudaGetSymbolAddress((void**)&bqkv, g_bqkv);

    const int SM128 = (BM + 128) * PADW * 4 * NSTG;            // 110592 B
    const int SM64  = (BM + 64)  * PADW * 4 * NSTG;            // 82944 B
    const int ATTN_SM = (4096 + 4096 + 64 * SCP + 64) * 4;     // ~116 KB
    cudaFuncSetAttribute(mma_gemm<64,  true,  true,  false, false>, cudaFuncAttributeMaxDynamicSharedMemorySize, SM64);
    cudaFuncSetAttribute(mma_gemm<64,  false, true,  false, true >, cudaFuncAttributeMaxDynamicSharedMemorySize, SM64);
    cudaFuncSetAttribute(mma_gemm<128, true,  true,  true,  false>, cudaFuncAttributeMaxDynamicSharedMemorySize, SM128);
    cudaFuncSetAttribute(mma_gemm<128, false, false, false, false>, cudaFuncAttributeMaxDynamicSharedMemorySize, SM128);
    cudaFuncSetAttribute(attn_tiled, cudaFuncAttributeMaxDynamicSharedMemorySize, ATTN_SM);

    // ---- launch 0: fused prep ----
    prep_all<<<TP_END, 256>>>(wq, wk, wv, wo, w1, w2, emb, bq, bk, bv);

    // ---- launch 1: embedding ----
    embed_kernel<<<(S * D + 255) / 256, 256>>>(ids, emb, pos);

    for (int l = 0; l < NL; ++l) {
        __half* base = wT + (size_t)l * 12 * MB_ELT;

        ln_kernel<<<S, 256>>>(x, h, ln1_g + l * D, ln1_b + l * D);

        // qkv = h @ Wqkv^T + b (N=3072, BNT=64 -> grid 768), half out
        mma_gemm<64, true, true, false, false><<<dim3(S / BM, 3 * D / 64), 256, SM64>>>(
            h, base + 0 * MB_ELT, bqkv + (size_t)l * 3 * D, nullptr, qkv, 3 * D, D);

        attn_tiled<<<dim3(S / TQ, H), 256, ATTN_SM>>>();

        // x = x + att @ wo^T + bo (fp32 out, grid 256)   <-- launch 5: ncu target
        mma_gemm<64, false, true, false, true><<<dim3(S / BM, D / 64), 256, SM64>>>(
            att, base + 3 * MB_ELT, bo + (size_t)l * D, x, x, D, D);

        ln_kernel<<<S, 256>>>(x, h, ln2_g + l * D, ln2_b + l * D);

        // ffn = gelu(h @ w1^T + b1), half out (grid 512)
        mma_gemm<128, true, true, true, false><<<dim3(S / BM, DF / 128), 256, SM128>>>(
            h, base + 4 * MB_ELT, b1 + (size_t)l * DF, nullptr, ffn, DF, D);

        // x = x + ffn @ w2^T + b2 (fp32 out, grid 256)
        mma_gemm<64, false, true, false, true><<<dim3(S / BM, D / 64), 256, SM64>>>(
            ffn, base + 8 * MB_ELT, b2 + (size_t)l * D, x, x, D, DF);
    }

    ln_kernel<<<S, 256>>>(x, h, out_g, out_b);

    // logits = h @ emb^T (fp32 out, grid 4000)
    mma_gemm<128, false, false, false, false><<<dim3(S / BM, VOCAB / 128), 256, SM128>>>(
        h, embT, nullptr, nullptr, logits, VOCAB, D);
}